// round 14
// baseline (speedup 1.0000x reference)
#include <cuda_runtime.h>
#include <cuda_fp16.h>
#include <cstdint>

#define NHEADS 20
#define HEAD_DIM 64
#define HIDDEN 1280
#define CROSS 2048
#define NB 4
#define SQ 4096
#define TXT 77
#define NTOK 4
#define ENC (TXT + NTOK)

// ============================================================================
// PTX helpers (baseline-family only: mma.sync / ldmatrix / cp.async)
// ============================================================================
__device__ __forceinline__ uint32_t smem_to_u32(const void* smem_ptr) {
    uint32_t addr;
    asm("{ .reg .u64 tmp; cvta.to.shared.u64 tmp, %1; cvt.u32.u64 %0, tmp; }"
        : "=r"(addr) : "l"(smem_ptr));
    return addr;
}

__device__ __forceinline__ void cp_async16(uint32_t dst, const void* src, int bytes) {
    asm volatile("cp.async.cg.shared.global [%0], [%1], 16, %2;"
                 :: "r"(dst), "l"(src), "r"(bytes));
}
#define CP_COMMIT() asm volatile("cp.async.commit_group;" ::: "memory")
#define CP_WAIT(N)  asm volatile("cp.async.wait_group %0;" :: "n"(N) : "memory")

__device__ __forceinline__ void ldsm_x4(uint32_t* r, uint32_t a) {
    asm volatile("ldmatrix.sync.aligned.m8n8.x4.shared.b16 {%0,%1,%2,%3}, [%4];"
                 : "=r"(r[0]), "=r"(r[1]), "=r"(r[2]), "=r"(r[3]) : "r"(a));
}

__device__ __forceinline__ void ldsm_x4_t(uint32_t* r, uint32_t a) {
    asm volatile("ldmatrix.sync.aligned.m8n8.x4.trans.shared.b16 {%0,%1,%2,%3}, [%4];"
                 : "=r"(r[0]), "=r"(r[1]), "=r"(r[2]), "=r"(r[3]) : "r"(a));
}

// f16 x f16 -> f32 MMA
__device__ __forceinline__ void mma16816(float* c, const uint32_t* a,
                                         uint32_t b0, uint32_t b1) {
    asm volatile(
        "mma.sync.aligned.m16n8k16.row.col.f32.f16.f16.f32 "
        "{%0,%1,%2,%3},{%4,%5,%6,%7},{%8,%9},{%0,%1,%2,%3};"
        : "+f"(c[0]), "+f"(c[1]), "+f"(c[2]), "+f"(c[3])
        : "r"(a[0]), "r"(a[1]), "r"(a[2]), "r"(a[3]), "r"(b0), "r"(b1));
}

__device__ __forceinline__ uint32_t pack_half2(float a, float b) {
    __half2 t;
    t.x = __float2half(a);
    t.y = __float2half(b);
    return *reinterpret_cast<uint32_t*>(&t);
}

// ============================================================================
// Scratch (static device allocations)
// ============================================================================
#define PART_STRIDE ((long)16 * TXT * HIDDEN)   // floats per split-K partial
#define NSPLIT 4

__device__ __half g_ahi[NB * SQ * HIDDEN];            // hidden-hi, then hs-hi
__device__ __half g_qhi[NB * SQ * HIDDEN];
__device__ __half g_ehi[NB * ENC * CROSS];
__device__ __half g_wqT[HIDDEN * HIDDEN];
__device__ __half g_wT[4 * HIDDEN * CROSS];           // wk, wv, wkip, wvip (T)
__device__ __half g_woutT[HIDDEN * HIDDEN];
__device__ __half g_kv[4 * NB * TXT * HIDDEN];        // k,v,ipk,ipv
__device__ float g_part[NSPLIT * 16 * TXT * HIDDEN];  // split-K partials

// ============================================================================
// fp32 -> fp16 convert (activations)
// ============================================================================
__global__ __launch_bounds__(256)
void split_hi_kernel(const float* __restrict__ in, __half* __restrict__ hi, int n4)
{
    int i = blockIdx.x * blockDim.x + threadIdx.x;
    if (i >= n4) return;
    float4 x = ((const float4*)in)[i];
    ((uint2*)hi)[i] = make_uint2(pack_half2(x.x, x.y), pack_half2(x.z, x.w));
}

// ============================================================================
// Merged transpose + fp16 convert of all 6 weights (grid.z selects weight).
// ============================================================================
struct TSArgs {
    const float* src[6];
    __half* dst[6];
    int K[6];
};

__global__ __launch_bounds__(256)
void transpose_all(TSArgs args)
{
    const int w = blockIdx.z;
    const int K = args.K[w];
    const int k0 = blockIdx.y * 32;
    if (k0 >= K) return;
    const float* in = args.src[w];
    __half* dst = args.dst[w];

    __shared__ float t[32][33];
    const int tx = threadIdx.x, ty = threadIdx.y;
    const int n0 = blockIdx.x * 32;
    #pragma unroll
    for (int j = ty; j < 32; j += 8)
        t[j][tx] = in[(long)(k0 + j) * HIDDEN + n0 + tx];
    __syncthreads();
    #pragma unroll
    for (int j = ty; j < 32; j += 8)
        dst[(long)(n0 + j) * K + k0 + tx] = __float2half(t[tx][j]);
}

// ============================================================================
// Shared GEMM pieces: CTA 128x128x64 (BK=64), 4 warps (128 thr), warp 64x64
// in 2x2 layout (dupA=dupB=2). cp.async double buffer, pure fp16.
// 144B rows (128B data + 16B pad, conflict-free).
// ============================================================================
#define LDS_ROW 144
#define OFF_A   0
#define OFF_B   18432
#define STGBUF  36864            // A + B per stage
#define SMEM_TOT 73728           // 2 stages (72KB; 2 CTAs = 144KB)

// Interleaved per-accumulator compute (do NOT burst-reorder; see R8).
// warp tile 64x64: mi 0..3 (A row frags), 2 col-quads of 32 cols each.
__device__ __forceinline__ void gemm_stage_compute(
    uint32_t base, uint32_t aoffs, uint32_t boffs, float acc[4][8][4])
{
    const uint32_t aA = base + OFF_A;
    const uint32_t bB = base + OFF_B;
    #pragma unroll
    for (int ks = 0; ks < 4; ks++) {
        uint32_t Ah[4][4];
        #pragma unroll
        for (int mi = 0; mi < 4; mi++)
            ldsm_x4(Ah[mi], aA + aoffs + mi * 16 * LDS_ROW + ks * 32);
        #pragma unroll
        for (int bq = 0; bq < 2; bq++) {
            uint32_t Bh[2][4];
            #pragma unroll
            for (int nn = 0; nn < 2; nn++)
                ldsm_x4(Bh[nn], bB + boffs + (bq * 2 + nn) * 16 * LDS_ROW + ks * 32);
            #pragma unroll
            for (int mi = 0; mi < 4; mi++) {
                #pragma unroll
                for (int j4 = 0; j4 < 4; j4++) {
                    const int ni = j4 >> 1, h = (j4 & 1) * 2;
                    mma16816(acc[mi][bq * 4 + j4], Ah[mi], Bh[ni][h], Bh[ni][h + 1]);
                }
            }
        }
    }
}

// kv packed-row map: parts 0-2 text K (4x77 rows), 3-5 text V, 6 ipK (16), 7 ipV.
__device__ __forceinline__ bool kv_map(int part, int r, long& aRow, long& cRow)
{
    aRow = 0; cRow = 0;
    if (part < 6) {
        int R = (part % 3) * 128 + r;
        if (R >= 4 * TXT) return false;
        int batch = R / TXT, rr = R - batch * TXT;
        aRow = (long)batch * ENC + rr;
        cRow = (long)(((part < 3 ? 0 : 1) * 4 + batch) * TXT + rr);
        return true;
    } else {
        if (r >= 16) return false;
        int batch = r >> 2, rr = r & 3;
        aRow = (long)batch * ENC + TXT + rr;
        cRow = (long)(((part == 6 ? 2 : 3) * 4 + batch) * TXT + rr);
        return true;
    }
}

// ============================================================================
// Merged Q-projection + packed split-K kv-projection GEMM.
// 1-D grid of 1600 CTAs: bid < 1280 -> Q tile (20 stages),
// bid >= 1280 -> kv tile (8 stages, 4 K-splits, backfills Q tail wave).
// ============================================================================
struct QKVArgs {
    const __half *ahi, *ehi;
    const __half *wq, *wt;
    __half *qhi;
    float* pbuf;
};

__global__ __launch_bounds__(128, 2)
void hmma_gemm_qkv(QKVArgs args)
{
    extern __shared__ __align__(16) char smx[];
    const uint32_t smb = smem_to_u32(smx);
    const int tid = threadIdx.x;
    const int bid = blockIdx.x;
    const bool isQ = bid < 1280;

    const int lr  = tid >> 3;      // 0..15
    const int cch = tid & 7;

    const __half *Ahi, *Bm;
    int K, NS, kBase, colBase, rowBase = 0, part = 0, split = 0;
    int aRow[8];
    int aBytes[8];

    if (isQ) {
        rowBase = (bid / 10) * 128;
        colBase = (bid % 10) * 128;
        Ahi = args.ahi;
        Bm = args.wq;
        K = HIDDEN; NS = 20; kBase = 0;
        #pragma unroll
        for (int i = 0; i < 8; i++) {
            aRow[i] = rowBase + lr + i * 16;
            aBytes[i] = 16;
        }
    } else {
        const int t = bid - 1280;
        colBase = (t % 10) * 128;
        part = (t / 10) & 7;
        split = t / 80;            // 0..3
        const int gemm = part < 3 ? 0 : (part < 6 ? 1 : (part == 6 ? 2 : 3));
        Ahi = args.ehi;
        Bm = args.wt + (long)gemm * HIDDEN * CROSS;
        K = CROSS; NS = 8; kBase = split * 512;
        #pragma unroll
        for (int i = 0; i < 8; i++) {
            long ar, cr;
            aBytes[i] = kv_map(part, lr + i * 16, ar, cr) ? 16 : 0;
            aRow[i] = (int)ar;
        }
    }

    const int warp = tid >> 5, lane = tid & 31;
    const int m0 = (warp >> 1) * 64, n0 = (warp & 1) * 64;

    const uint32_t aoffs = (uint32_t)((m0 + (lane & 15)) * LDS_ROW + (lane >> 4) * 16);
    const uint32_t boffs = (uint32_t)((n0 + ((lane >> 4) & 1) * 8 + (lane & 7)) * LDS_ROW
                                      + ((lane >> 3) & 1) * 16);

    float acc[4][8][4];
    #pragma unroll
    for (int mi = 0; mi < 4; mi++)
        #pragma unroll
        for (int nj = 0; nj < 8; nj++)
            #pragma unroll
            for (int t = 0; t < 4; t++) acc[mi][nj][t] = 0.f;

    auto load_stage = [&](int s) {
        const int b = s & 1;
        const int k0 = kBase + (s << 6);
        #pragma unroll
        for (int i = 0; i < 8; i++) {
            const int r = lr + i * 16;
            uint32_t d = smb + (uint32_t)(b * STGBUF + r * LDS_ROW + cch * 16);
            long go = (long)aRow[i] * K + k0 + cch * 8;
            cp_async16(d + OFF_A, Ahi + go, aBytes[i]);
            long gb = (long)(colBase + r) * K + k0 + cch * 8;
            cp_async16(d + OFF_B, Bm + gb, 16);
        }
        CP_COMMIT();
    };

    load_stage(0);
    for (int s = 0; s < NS; ++s) {
        if (s + 1 < NS) {
            load_stage(s + 1);
            CP_WAIT(1);
        } else {
            CP_WAIT(0);
        }
        __syncthreads();
        gemm_stage_compute(smb + (s & 1) * STGBUF, aoffs, boffs, acc);
        __syncthreads();
    }

    // Epilogue
    const int g = lane >> 2, tig = lane & 3;
    if (isQ) {
        #pragma unroll
        for (int mi = 0; mi < 4; mi++) {
            #pragma unroll
            for (int nj = 0; nj < 8; nj++) {
                const int r0 = rowBase + m0 + mi * 16 + g;
                const int col = colBase + n0 + nj * 8 + tig * 2;
                #pragma unroll
                for (int rr = 0; rr < 2; rr++) {
                    long o = (long)(r0 + rr * 8) * HIDDEN + col;
                    *(uint32_t*)(args.qhi + o) =
                        pack_half2(acc[mi][nj][rr * 2 + 0], acc[mi][nj][rr * 2 + 1]);
                }
            }
        }
    } else {
        float* pout = args.pbuf + (long)split * PART_STRIDE;
        #pragma unroll
        for (int mi = 0; mi < 4; mi++) {
            #pragma unroll
            for (int nj = 0; nj < 8; nj++) {
                const int r0 = m0 + mi * 16 + g;
                const int col = colBase + n0 + nj * 8 + tig * 2;
                long aR, cR;
                if (kv_map(part, r0, aR, cR))
                    *(float2*)(pout + cR * HIDDEN + col) =
                        make_float2(acc[mi][nj][0], acc[mi][nj][1]);
                if (kv_map(part, r0 + 8, aR, cR))
                    *(float2*)(pout + cR * HIDDEN + col) =
                        make_float2(acc[mi][nj][2], acc[mi][nj][3]);
            }
        }
    }
}

// ============================================================================
// Out-projection GEMM (BK=64, warp 64x64, pure fp16, fused bias+resid).
// ============================================================================
struct GemmArgs {
    const __half *Ahi, *Bm;
    float* C;
    int K, ldc;
    const float *bias, *resid;
};

__global__ __launch_bounds__(128, 2)
void hmma_gemm(GemmArgs args)
{
    extern __shared__ __align__(16) char smx[];
    const uint32_t smb = smem_to_u32(smx);
    const int tid = threadIdx.x;

    const __half* Ahi = args.Ahi;
    const __half* Bm = args.Bm;
    const int K = args.K, ldc = args.ldc;

    const int rowBase = blockIdx.y * 128;
    const int colBase = blockIdx.x * 128;
    const int NS = K >> 6;
    const int lr  = tid >> 3;
    const int cch = tid & 7;

    const int warp = tid >> 5, lane = tid & 31;
    const int m0 = (warp >> 1) * 64, n0 = (warp & 1) * 64;

    const uint32_t aoffs = (uint32_t)((m0 + (lane & 15)) * LDS_ROW + (lane >> 4) * 16);
    const uint32_t boffs = (uint32_t)((n0 + ((lane >> 4) & 1) * 8 + (lane & 7)) * LDS_ROW
                                      + ((lane >> 3) & 1) * 16);

    float acc[4][8][4];
    #pragma unroll
    for (int mi = 0; mi < 4; mi++)
        #pragma unroll
        for (int nj = 0; nj < 8; nj++)
            #pragma unroll
            for (int t = 0; t < 4; t++) acc[mi][nj][t] = 0.f;

    auto load_stage = [&](int s) {
        const int b = s & 1;
        const long k0 = (long)s << 6;
        #pragma unroll
        for (int i = 0; i < 8; i++) {
            const int r = lr + i * 16;
            uint32_t d = smb + (uint32_t)(b * STGBUF + r * LDS_ROW + cch * 16);
            long go = (long)(rowBase + r) * K + k0 + cch * 8;
            cp_async16(d + OFF_A, Ahi + go, 16);
            long gb = (long)(colBase + r) * K + k0 + cch * 8;
            cp_async16(d + OFF_B, Bm + gb, 16);
        }
        CP_COMMIT();
    };

    load_stage(0);
    for (int s = 0; s < NS; ++s) {
        if (s + 1 < NS) {
            load_stage(s + 1);
            CP_WAIT(1);
        } else {
            CP_WAIT(0);
        }
        __syncthreads();
        gemm_stage_compute(smb + (s & 1) * STGBUF, aoffs, boffs, acc);
        __syncthreads();
    }

    // Epilogue: fp32 + bias + residual
    const int g = lane >> 2, tig = lane & 3;
    const float* bias = args.bias;
    const float* resid = args.resid;
    #pragma unroll
    for (int mi = 0; mi < 4; mi++) {
        #pragma unroll
        for (int nj = 0; nj < 8; nj++) {
            const int r0 = rowBase + m0 + mi * 16 + g;
            const int col = colBase + n0 + nj * 8 + tig * 2;
            float2 v0 = make_float2(acc[mi][nj][0], acc[mi][nj][1]);
            float2 v1 = make_float2(acc[mi][nj][2], acc[mi][nj][3]);
            const float2 bi = *(const float2*)(bias + col);
            v0.x += bi.x; v0.y += bi.y;
            v1.x += bi.x; v1.y += bi.y;
            const float2 rr0 = *(const float2*)(resid + (long)r0 * ldc + col);
            v0.x += rr0.x; v0.y += rr0.y;
            const float2 rr1 = *(const float2*)(resid + (long)(r0 + 8) * ldc + col);
            v1.x += rr1.x; v1.y += rr1.y;
            *(float2*)(args.C + (long)r0 * ldc + col)       = v0;
            *(float2*)(args.C + (long)(r0 + 8) * ldc + col) = v1;
        }
    }
}

// Sum NSPLIT split-K partials -> kv fp16.
__global__ __launch_bounds__(256)
void reduce_split_kv(const float* __restrict__ part, __half* __restrict__ hi)
{
    const long n4 = PART_STRIDE / 4;
    long i = (long)blockIdx.x * 256 + threadIdx.x;
    if (i >= n4) return;
    const float4* p4 = (const float4*)part;
    float4 s = p4[i];
    #pragma unroll
    for (int k = 1; k < NSPLIT; k++) {
        float4 t = p4[i + (long)k * n4];
        s.x += t.x; s.y += t.y; s.z += t.z; s.w += t.w;
    }
    ((uint2*)hi)[i] = make_uint2(pack_half2(s.x, s.y), pack_half2(s.z, s.w));
}

// ============================================================================
// HMMA flash attention: CTA = 128 q-rows x 96 keys (77 text + pad + 4 ip @80).
// 8 warps, warp = 16 rows. Pure fp16. V [key][dim] + ldsm.trans.
// Writes hs as fp16.
// ============================================================================
#define AROW 144
#define KROW 144
#define OFF_Q  0
#define OFF_K  (128 * AROW)                 // 18432
#define OFF_V  (OFF_K + 96 * KROW)          // 32256
#define SMEM_ATTN (OFF_V + 96 * KROW)       // 46080

__global__ __launch_bounds__(256)
void attn_mma(const __half* __restrict__ qhi,
              const __half* __restrict__ kv,
              __half* __restrict__ ohi)
{
    extern __shared__ __align__(16) char smx[];
    const uint32_t smb = smem_to_u32(smx);
    const int tid = threadIdx.x;
    const int b = blockIdx.z, h = blockIdx.y;
    const int rowBase = blockIdx.x * 128;
    const long SLAB = (long)NB * TXT * HIDDEN;

    // Q tile: 128 rows x 64 dims
    #pragma unroll
    for (int i = 0; i < 4; i++) {
        int idx = tid + i * 256;
        int r = idx >> 3, c = idx & 7;
        long src = ((long)b * SQ + rowBase + r) * HIDDEN + h * 64 + c * 8;
        cp_async16(smb + OFF_Q + (uint32_t)(r * AROW + c * 16), qhi + src, 16);
    }
    // K tile: rows 0-76 text K, 80-83 ipK, rest zero
    #pragma unroll
    for (int i = 0; i < 3; i++) {
        int idx = tid + i * 256;
        int r = idx >> 3, c = idx & 7;
        int bytes = 0;
        long src = 0;
        if (r < TXT) {
            bytes = 16;
            src = (long)b * TXT * HIDDEN + (long)r * HIDDEN + h * 64 + c * 8;
        } else if (r >= 80 && r < 80 + NTOK) {
            bytes = 16;
            src = 2 * SLAB + (long)b * TXT * HIDDEN + (long)(r - 80) * HIDDEN + h * 64 + c * 8;
        }
        cp_async16(smb + OFF_K + (uint32_t)(r * KROW + c * 16), kv + src, bytes);
    }
    // V tile: rows 0-76 text V, 80-83 ipV, [key][dim]
    #pragma unroll
    for (int i = 0; i < 3; i++) {
        int idx = tid + i * 256;
        int r = idx >> 3, c = idx & 7;
        int bytes = 0;
        long src = 0;
        if (r < TXT) {
            bytes = 16;
            src = SLAB + (long)b * TXT * HIDDEN + (long)r * HIDDEN + h * 64 + c * 8;
        } else if (r >= 80 && r < 80 + NTOK) {
            bytes = 16;
            src = 3 * SLAB + (long)b * TXT * HIDDEN + (long)(r - 80) * HIDDEN + h * 64 + c * 8;
        }
        cp_async16(smb + OFF_V + (uint32_t)(r * KROW + c * 16), kv + src, bytes);
    }
    CP_COMMIT();
    CP_WAIT(0);
    __syncthreads();

    const int warp = tid >> 5, lane = tid & 31;
    const int m0 = warp * 16;
    const int tig = lane & 3;
    const uint32_t aoffs = smb + OFF_Q + (uint32_t)((m0 + (lane & 15)) * AROW + (lane >> 4) * 16);
    const uint32_t kbase = smb + OFF_K
        + (uint32_t)((((lane >> 4) & 1) * 8 + (lane & 7)) * KROW + ((lane >> 3) & 1) * 16);

    // S = Q K^T (12 n-tiles of 8 keys = 96)
    float s[12][4];
    #pragma unroll
    for (int j = 0; j < 12; j++)
        #pragma unroll
        for (int e = 0; e < 4; e++) s[j][e] = 0.f;

    #pragma unroll
    for (int ks = 0; ks < 4; ks++) {
        uint32_t Qh[4];
        ldsm_x4(Qh, aoffs + ks * 32);
        #pragma unroll
        for (int t = 0; t < 6; t++) {
            uint32_t Bh[4];
            ldsm_x4(Bh, kbase + t * 16 * KROW + ks * 32);
            mma16816(s[2 * t + 0], Qh, Bh[0], Bh[1]);
            mma16816(s[2 * t + 1], Qh, Bh[2], Bh[3]);
        }
    }

    // scale + mask + dual softmax
    const bool ipOn = (b & 1);
    float mx[2]  = {-1e30f, -1e30f};
    float mx2[2] = {-1e30f, -1e30f};
    #pragma unroll
    for (int j = 0; j < 10; j++)
        #pragma unroll
        for (int e = 0; e < 4; e++) {
            int col = j * 8 + tig * 2 + (e & 1);
            float v = s[j][e] * 0.125f;
            s[j][e] = (col < TXT) ? v : -1e30f;
            mx[e >> 1] = fmaxf(mx[e >> 1], s[j][e]);
        }
    #pragma unroll
    for (int j = 10; j < 12; j++)
        #pragma unroll
        for (int e = 0; e < 4; e++) {
            int col = j * 8 + tig * 2 + (e & 1);
            float v = s[j][e] * 0.125f;
            s[j][e] = (col >= 80 && col < 80 + NTOK) ? v : -1e30f;
            mx2[e >> 1] = fmaxf(mx2[e >> 1], s[j][e]);
        }
    #pragma unroll
    for (int off = 1; off <= 2; off <<= 1) {
        mx[0]  = fmaxf(mx[0],  __shfl_xor_sync(0xffffffffu, mx[0],  off));
        mx[1]  = fmaxf(mx[1],  __shfl_xor_sync(0xffffffffu, mx[1],  off));
        mx2[0] = fmaxf(mx2[0], __shfl_xor_sync(0xffffffffu, mx2[0], off));
        mx2[1] = fmaxf(mx2[1], __shfl_xor_sync(0xffffffffu, mx2[1], off));
    }
    float l[2] = {0.f, 0.f}, l2[2] = {0.f, 0.f};
    #pragma unroll
    for (int j = 0; j < 10; j++)
        #pragma unroll
        for (int e = 0; e < 4; e++) {
            float p = __expf(s[j][e] - mx[e >> 1]);
            s[j][e] = p;
            l[e >> 1] += p;
        }
    #pragma unroll
    for (int j = 10; j < 12; j++)
        #pragma unroll
        for (int e = 0; e < 4; e++) {
            float p = __expf(s[j][e] - mx2[e >> 1]);
            s[j][e] = p;
            l2[e >> 1] += p;
        }
    #pragma unroll
    for (int off = 1; off <= 2; off <<= 1) {
        l[0]  += __shfl_xor_sync(0xffffffffu, l[0],  off);
        l[1]  += __shfl_xor_sync(0xffffffffu, l[1],  off);
        l2[0] += __shfl_xor_sync(0xffffffffu, l2[0], off);
        l2[1] += __shfl_xor_sync(0xffffffffu, l2[1], off);
    }
    float inv[2], inv2[2];
    inv[0] = 1.f / l[0];
    inv[1] = 1.f / l[1];
    inv2[0] = ipOn ? 1.f / l2[0] : 0.f;
    inv2[1] = ipOn ? 1.f / l2[1] : 0.f;
    #pragma unroll
    for (int j = 0; j < 10; j++)
        #pragma unroll
        for (int e = 0; e < 4; e++) s[j][e] *= inv[e >> 1];
    #pragma unroll
    for (int j = 10; j < 12; j++)
        #pragma unroll
        for (int e = 0; e < 4; e++) s[j][e] *= inv2[e >> 1];

    // PV via ldsm.trans on V[key][dim]
    const uint32_t vtbase = smb + OFF_V
        + (uint32_t)((((lane >> 3) & 1) * 8 + (lane & 7)) * KROW + ((lane >> 4) & 1) * 16);
    float out[8][4];
    #pragma unroll
    for (int d = 0; d < 8; d++)
        #pragma unroll
        for (int e = 0; e < 4; e++) out[d][e] = 0.f;

    #pragma unroll
    for (int kk = 0; kk < 6; kk++) {
        uint32_t ah[4];
        #pragma unroll
        for (int r = 0; r < 4; r++) {
            const int t = 2 * kk + (r >> 1);
            const int pi = (r & 1) * 2;
            ah[r] = pack_half2(s[t][pi], s[t][pi + 1]);
        }
        #pragma unroll
        for (int d = 0; d < 4; d++) {
            uint32_t Vh[4];
            ldsm_x4_t(Vh, vtbase + kk * 16 * KROW + d * 32);
            mma16816(out[2 * d + 0], ah, Vh[0], Vh[1]);
            mma16816(out[2 * d + 1], ah, Vh[2], Vh[3]);
        }
    }

    // write hs fp16
    const int g = lane >> 2;
    const long row0 = (long)b * SQ + rowBase + m0 + g;
    #pragma unroll
    for (int d = 0; d < 8; d++) {
        const int col = h * 64 + d * 8 + tig * 2;
        #pragma unroll
        for (int rr = 0; rr < 2; rr++) {
            long o = (row0 + rr * 8) * HIDDEN + col;
            *(uint32_t*)(ohi + o) = pack_half2(out[d][rr * 2 + 0], out[d][rr * 2 + 1]);
        }
    }
}

// ============================================================================
// Launcher
// ============================================================================
extern "C" void kernel_launch(void* const* d_in, const int* in_sizes, int n_in,
                              void* d_out, int out_size)
{
    const float* hidden = (const float*)d_in[0];
    const float* enc    = (const float*)d_in[1];
    const float* Wq     = (const float*)d_in[2];
    const float* Wk     = (const float*)d_in[3];
    const float* Wv     = (const float*)d_in[4];
    const float* Wk_ip  = (const float*)d_in[5];
    const float* Wv_ip  = (const float*)d_in[6];
    const float* Wout   = (const float*)d_in[7];
    const float* b_out  = (const float*)d_in[8];
    float* out = (float*)d_out;

    static bool attr_set = false;
    if (!attr_set) {
        cudaFuncSetAttribute(hmma_gemm, cudaFuncAttributeMaxDynamicSharedMemorySize, SMEM_TOT);
        cudaFuncSetAttribute(hmma_gemm_qkv, cudaFuncAttributeMaxDynamicSharedMemorySize, SMEM_TOT);
        cudaFuncSetAttribute(attn_mma, cudaFuncAttributeMaxDynamicSharedMemorySize, SMEM_ATTN);
        attr_set = true;
    }

    __half *ahi, *qhi, *ehi, *wq, *wt, *wo, *kv;
    float* pbuf;
    cudaGetSymbolAddress((void**)&ahi, g_ahi);
    cudaGetSymbolAddress((void**)&qhi, g_qhi);
    cudaGetSymbolAddress((void**)&ehi, g_ehi);
    cudaGetSymbolAddress((void**)&wq,  g_wqT);
    cudaGetSymbolAddress((void**)&wt,  g_wT);
    cudaGetSymbolAddress((void**)&wo,  g_woutT);
    cudaGetSymbolAddress((void**)&kv,  g_kv);
    cudaGetSymbolAddress((void**)&pbuf, g_part);

    const int M_big = NB * SQ;  // 16384
    const long WSLAB = (long)HIDDEN * CROSS;

    // 1) activation fp16 converts
    {
        int n4 = M_big * HIDDEN / 4;
        split_hi_kernel<<<(n4 + 255) / 256, 256>>>(hidden, ahi, n4);
    }
    {
        int n4 = NB * ENC * CROSS / 4;
        split_hi_kernel<<<(n4 + 255) / 256, 256>>>(enc, ehi, n4);
    }

    // 2) all weight transposes in one launch
    {
        TSArgs t;
        t.src[0] = Wq;    t.dst[0] = wq;             t.K[0] = HIDDEN;
        t.src[1] = Wk;    t.dst[1] = wt + 0 * WSLAB; t.K[1] = CROSS;
        t.src[2] = Wv;    t.dst[2] = wt + 1 * WSLAB; t.K[2] = CROSS;
        t.src[3] = Wk_ip; t.dst[3] = wt + 2 * WSLAB; t.K[3] = CROSS;
        t.src[4] = Wv_ip; t.dst[4] = wt + 3 * WSLAB; t.K[4] = CROSS;
        t.src[5] = Wout;  t.dst[5] = wo;             t.K[5] = HIDDEN;
        transpose_all<<<dim3(HIDDEN / 32, CROSS / 32, 6), dim3(32, 8)>>>(t);
    }

    // 3) merged Q projection + packed split-K kv projections (1600 CTAs)
    {
        QKVArgs a;
        a.ahi = ahi; a.ehi = ehi;
        a.wq = wq; a.wt = wt;
        a.qhi = qhi; a.pbuf = pbuf;
        hmma_gemm_qkv<<<1280 + NSPLIT * 80, 128, SMEM_TOT>>>(a);
    }

    // 4) reduce split-K partials -> kv fp16
    {
        long n4 = PART_STRIDE / 4;
        reduce_split_kv<<<(int)((n4 + 255) / 256), 256>>>(pbuf, kv);
    }

    // 5) HMMA attention -> hs fp16 (reuses g_ahi)
    attn_mma<<<dim3(SQ / 128, NHEADS, NB), 256, SMEM_ATTN>>>(qhi, kv, ahi);

    // 6) out = hs @ Wout + b_out + residual (fp32)
    {
        GemmArgs a = {ahi, wo, out, HIDDEN, HIDDEN, b_out, hidden};
        hmma_gemm<<<dim3(HIDDEN / 128, M_big / 128, 1), 128, SMEM_TOT>>>(a);
    }
}

// round 15
// speedup vs baseline: 1.1627x; 1.1627x over previous
#include <cuda_runtime.h>
#include <cuda_fp16.h>
#include <cstdint>

#define NHEADS 20
#define HEAD_DIM 64
#define HIDDEN 1280
#define CROSS 2048
#define NB 4
#define SQ 4096
#define TXT 77
#define NTOK 4
#define ENC (TXT + NTOK)

// ============================================================================
// PTX helpers (baseline-family only: mma.sync / ldmatrix / cp.async)
// ============================================================================
__device__ __forceinline__ uint32_t smem_to_u32(const void* smem_ptr) {
    uint32_t addr;
    asm("{ .reg .u64 tmp; cvta.to.shared.u64 tmp, %1; cvt.u32.u64 %0, tmp; }"
        : "=r"(addr) : "l"(smem_ptr));
    return addr;
}

__device__ __forceinline__ void cp_async16(uint32_t dst, const void* src, int bytes) {
    asm volatile("cp.async.cg.shared.global [%0], [%1], 16, %2;"
                 :: "r"(dst), "l"(src), "r"(bytes));
}
#define CP_COMMIT() asm volatile("cp.async.commit_group;" ::: "memory")
#define CP_WAIT(N)  asm volatile("cp.async.wait_group %0;" :: "n"(N) : "memory")

__device__ __forceinline__ void ldsm_x4(uint32_t* r, uint32_t a) {
    asm volatile("ldmatrix.sync.aligned.m8n8.x4.shared.b16 {%0,%1,%2,%3}, [%4];"
                 : "=r"(r[0]), "=r"(r[1]), "=r"(r[2]), "=r"(r[3]) : "r"(a));
}

__device__ __forceinline__ void ldsm_x4_t(uint32_t* r, uint32_t a) {
    asm volatile("ldmatrix.sync.aligned.m8n8.x4.trans.shared.b16 {%0,%1,%2,%3}, [%4];"
                 : "=r"(r[0]), "=r"(r[1]), "=r"(r[2]), "=r"(r[3]) : "r"(a));
}

// f16 x f16 -> f32 MMA
__device__ __forceinline__ void mma16816(float* c, const uint32_t* a,
                                         uint32_t b0, uint32_t b1) {
    asm volatile(
        "mma.sync.aligned.m16n8k16.row.col.f32.f16.f16.f32 "
        "{%0,%1,%2,%3},{%4,%5,%6,%7},{%8,%9},{%0,%1,%2,%3};"
        : "+f"(c[0]), "+f"(c[1]), "+f"(c[2]), "+f"(c[3])
        : "r"(a[0]), "r"(a[1]), "r"(a[2]), "r"(a[3]), "r"(b0), "r"(b1));
}

__device__ __forceinline__ uint32_t pack_half2(float a, float b) {
    __half2 t;
    t.x = __float2half(a);
    t.y = __float2half(b);
    return *reinterpret_cast<uint32_t*>(&t);
}

// ============================================================================
// Scratch (static device allocations)
// ============================================================================
#define PART_STRIDE ((long)16 * TXT * HIDDEN)   // floats per split-K partial
#define NSPLIT 8

__device__ __half g_ahi[NB * SQ * HIDDEN];            // hidden-hi, then hs-hi
__device__ __half g_qhi[NB * SQ * HIDDEN];
__device__ __half g_ehi[NB * ENC * CROSS];
__device__ __half g_wqT[HIDDEN * HIDDEN];
__device__ __half g_wT[4 * HIDDEN * CROSS];           // wk, wv, wkip, wvip (T)
__device__ __half g_woutT[HIDDEN * HIDDEN];
__device__ __half g_kv[4 * NB * TXT * HIDDEN];        // k,v,ipk,ipv
__device__ float g_part[NSPLIT * 16 * TXT * HIDDEN];  // split-K partials

// ============================================================================
// Merged prep: weight transposes + activation fp16 converts, one launch.
// bid ranges: [0, NT_BLK) transpose (w = t/2560, n0/k0 from rem),
//             [NT_BLK, NT_BLK+NE_BLK) enc convert,
//             [NT_BLK+NE_BLK, +NH_BLK) hidden convert.
// ============================================================================
#define NT_BLK (40 * 64 * 6)                       // 15360
#define NE_BLK ((NB * ENC * CROSS / 4 + 255) / 256)   // 648
#define NH_BLK ((NB * SQ * HIDDEN / 4 + 255) / 256)   // 20480

struct PrepArgs {
    const float* wsrc[6];
    __half* wdst[6];
    int K[6];
    const float* hidden;
    const float* enc;
    __half* ahi;
    __half* ehi;
};

__global__ __launch_bounds__(256)
void prep_all(PrepArgs p)
{
    const int bid = blockIdx.x;
    const int tid = threadIdx.x;

    if (bid < NT_BLK) {
        // transpose + convert: block (32x8 logical)
        const int t = bid;
        const int w = t / 2560;
        const int rem = t % 2560;
        const int n0 = (rem % 40) * 32;
        const int k0 = (rem / 40) * 32;
        const int K = p.K[w];
        if (k0 >= K) return;
        const float* in = p.wsrc[w];
        __half* dst = p.wdst[w];

        __shared__ float tb[32][33];
        const int tx = tid & 31, ty = tid >> 5;
        #pragma unroll
        for (int j = ty; j < 32; j += 8)
            tb[j][tx] = in[(long)(k0 + j) * HIDDEN + n0 + tx];
        __syncthreads();
        #pragma unroll
        for (int j = ty; j < 32; j += 8)
            dst[(long)(n0 + j) * K + k0 + tx] = __float2half(tb[tx][j]);
    } else if (bid < NT_BLK + NE_BLK) {
        const int i = (bid - NT_BLK) * 256 + tid;
        const int n4 = NB * ENC * CROSS / 4;
        if (i >= n4) return;
        float4 x = ((const float4*)p.enc)[i];
        ((uint2*)p.ehi)[i] = make_uint2(pack_half2(x.x, x.y), pack_half2(x.z, x.w));
    } else {
        const int i = (bid - NT_BLK - NE_BLK) * 256 + tid;
        const int n4 = NB * SQ * HIDDEN / 4;
        if (i >= n4) return;
        float4 x = ((const float4*)p.hidden)[i];
        ((uint2*)p.ahi)[i] = make_uint2(pack_half2(x.x, x.y), pack_half2(x.z, x.w));
    }
}

// ============================================================================
// Shared GEMM pieces (R12 config): CTA 128x128x64 (BK=64), 8 warps (256 thr),
// warp 32x64, cp.async double buffer, pure fp16.
// 144B rows (128B data + 16B pad, conflict-free).
// ============================================================================
#define LDS_ROW 144
#define OFF_A   0
#define OFF_B   18432
#define STGBUF  36864            // A + B per stage
#define SMEM_TOT 73728           // 2 stages

// Interleaved per-accumulator compute (do NOT burst-reorder; see R8).
__device__ __forceinline__ void gemm_stage_compute(
    uint32_t base, uint32_t aoffs, uint32_t boffs, float acc[2][8][4])
{
    const uint32_t aA = base + OFF_A;
    const uint32_t bB = base + OFF_B;
    #pragma unroll
    for (int ks = 0; ks < 4; ks++) {
        uint32_t Ah[2][4];
        #pragma unroll
        for (int mi = 0; mi < 2; mi++)
            ldsm_x4(Ah[mi], aA + aoffs + mi * 16 * LDS_ROW + ks * 32);
        #pragma unroll
        for (int half = 0; half < 2; half++) {
            uint32_t Bh[2][4];
            #pragma unroll
            for (int nn = 0; nn < 2; nn++)
                ldsm_x4(Bh[nn], bB + boffs + (half * 2 + nn) * 16 * LDS_ROW + ks * 32);
            #pragma unroll
            for (int mi = 0; mi < 2; mi++) {
                #pragma unroll
                for (int j4 = 0; j4 < 4; j4++) {
                    const int ni = j4 >> 1, h = (j4 & 1) * 2;
                    mma16816(acc[mi][half * 4 + j4], Ah[mi], Bh[ni][h], Bh[ni][h + 1]);
                }
            }
        }
    }
}

// kv packed-row map: parts 0-2 text K (4x77 rows), 3-5 text V, 6 ipK (16), 7 ipV.
__device__ __forceinline__ bool kv_map(int part, int r, long& aRow, long& cRow)
{
    aRow = 0; cRow = 0;
    if (part < 6) {
        int R = (part % 3) * 128 + r;
        if (R >= 4 * TXT) return false;
        int batch = R / TXT, rr = R - batch * TXT;
        aRow = (long)batch * ENC + rr;
        cRow = (long)(((part < 3 ? 0 : 1) * 4 + batch) * TXT + rr);
        return true;
    } else {
        if (r >= 16) return false;
        int batch = r >> 2, rr = r & 3;
        aRow = (long)batch * ENC + TXT + rr;
        cRow = (long)(((part == 6 ? 2 : 3) * 4 + batch) * TXT + rr);
        return true;
    }
}

// ============================================================================
// Merged Q-projection + packed split-K kv-projection GEMM (BK=64).
// 1-D grid of 1920 CTAs: bid < 1280 -> Q tile (20 stages),
// bid >= 1280 -> kv tile (4 stages, 8 K-splits, backfills Q tail wave).
// ============================================================================
struct QKVArgs {
    const __half *ahi, *ehi;
    const __half *wq, *wt;
    __half *qhi;
    float* pbuf;
};

__global__ __launch_bounds__(256, 2)
void hmma_gemm_qkv(QKVArgs args)
{
    extern __shared__ __align__(16) char smx[];
    const uint32_t smb = smem_to_u32(smx);
    const int tid = threadIdx.x;
    const int bid = blockIdx.x;
    const bool isQ = bid < 1280;

    const int lr  = tid >> 3;
    const int cch = tid & 7;

    const __half *Ahi, *Bm;
    int K, NS, kBase, colBase, rowBase = 0, part = 0, split = 0;
    int aRow[4];
    int aBytes[4];

    if (isQ) {
        rowBase = (bid / 10) * 128;
        colBase = (bid % 10) * 128;
        Ahi = args.ahi;
        Bm = args.wq;
        K = HIDDEN; NS = 20; kBase = 0;
        #pragma unroll
        for (int i = 0; i < 4; i++) {
            aRow[i] = rowBase + lr + i * 32;
            aBytes[i] = 16;
        }
    } else {
        const int t = bid - 1280;
        colBase = (t % 10) * 128;
        part = (t / 10) & 7;
        split = t / 80;
        const int gemm = part < 3 ? 0 : (part < 6 ? 1 : (part == 6 ? 2 : 3));
        Ahi = args.ehi;
        Bm = args.wt + (long)gemm * HIDDEN * CROSS;
        K = CROSS; NS = 4; kBase = split * 256;
        #pragma unroll
        for (int i = 0; i < 4; i++) {
            long ar, cr;
            aBytes[i] = kv_map(part, lr + i * 32, ar, cr) ? 16 : 0;
            aRow[i] = (int)ar;
        }
    }

    const int warp = tid >> 5, lane = tid & 31;
    const int wm = warp >> 1, wn = warp & 1;
    const int m0 = wm * 32, n0 = wn * 64;

    const uint32_t aoffs = (uint32_t)((m0 + (lane & 15)) * LDS_ROW + (lane >> 4) * 16);
    const uint32_t boffs = (uint32_t)((n0 + ((lane >> 4) & 1) * 8 + (lane & 7)) * LDS_ROW
                                      + ((lane >> 3) & 1) * 16);

    float acc[2][8][4];
    #pragma unroll
    for (int mi = 0; mi < 2; mi++)
        #pragma unroll
        for (int nj = 0; nj < 8; nj++)
            #pragma unroll
            for (int t = 0; t < 4; t++) acc[mi][nj][t] = 0.f;

    auto load_stage = [&](int s) {
        const int b = s & 1;
        const int k0 = kBase + (s << 6);
        #pragma unroll
        for (int i = 0; i < 4; i++) {
            const int r = lr + i * 32;
            uint32_t d = smb + (uint32_t)(b * STGBUF + r * LDS_ROW + cch * 16);
            long go = (long)aRow[i] * K + k0 + cch * 8;
            cp_async16(d + OFF_A, Ahi + go, aBytes[i]);
            long gb = (long)(colBase + r) * K + k0 + cch * 8;
            cp_async16(d + OFF_B, Bm + gb, 16);
        }
        CP_COMMIT();
    };

    load_stage(0);
    for (int s = 0; s < NS; ++s) {
        if (s + 1 < NS) {
            load_stage(s + 1);
            CP_WAIT(1);
        } else {
            CP_WAIT(0);
        }
        __syncthreads();
        gemm_stage_compute(smb + (s & 1) * STGBUF, aoffs, boffs, acc);
        __syncthreads();
    }

    // Epilogue
    const int g = lane >> 2, tig = lane & 3;
    if (isQ) {
        #pragma unroll
        for (int mi = 0; mi < 2; mi++) {
            #pragma unroll
            for (int nj = 0; nj < 8; nj++) {
                const int r0 = rowBase + m0 + mi * 16 + g;
                const int col = colBase + n0 + nj * 8 + tig * 2;
                #pragma unroll
                for (int rr = 0; rr < 2; rr++) {
                    long o = (long)(r0 + rr * 8) * HIDDEN + col;
                    *(uint32_t*)(args.qhi + o) =
                        pack_half2(acc[mi][nj][rr * 2 + 0], acc[mi][nj][rr * 2 + 1]);
                }
            }
        }
    } else {
        float* pout = args.pbuf + (long)split * PART_STRIDE;
        #pragma unroll
        for (int mi = 0; mi < 2; mi++) {
            #pragma unroll
            for (int nj = 0; nj < 8; nj++) {
                const int r0 = m0 + mi * 16 + g;
                const int col = colBase + n0 + nj * 8 + tig * 2;
                long aR, cR;
                if (kv_map(part, r0, aR, cR))
                    *(float2*)(pout + cR * HIDDEN + col) =
                        make_float2(acc[mi][nj][0], acc[mi][nj][1]);
                if (kv_map(part, r0 + 8, aR, cR))
                    *(float2*)(pout + cR * HIDDEN + col) =
                        make_float2(acc[mi][nj][2], acc[mi][nj][3]);
            }
        }
    }
}

// ============================================================================
// Out-projection GEMM (BK=64, pure fp16, fused bias+resid).
// ============================================================================
struct GemmArgs {
    const __half *Ahi, *Bm;
    float* C;
    int K, ldc;
    const float *bias, *resid;
};

__global__ __launch_bounds__(256, 2)
void hmma_gemm(GemmArgs args)
{
    extern __shared__ __align__(16) char smx[];
    const uint32_t smb = smem_to_u32(smx);
    const int tid = threadIdx.x;

    const __half* Ahi = args.Ahi;
    const __half* Bm = args.Bm;
    const int K = args.K, ldc = args.ldc;

    const int rowBase = blockIdx.y * 128;
    const int colBase = blockIdx.x * 128;
    const int NS = K >> 6;
    const int lr  = tid >> 3;
    const int cch = tid & 7;

    const int warp = tid >> 5, lane = tid & 31;
    const int wm = warp >> 1, wn = warp & 1;
    const int m0 = wm * 32, n0 = wn * 64;

    const uint32_t aoffs = (uint32_t)((m0 + (lane & 15)) * LDS_ROW + (lane >> 4) * 16);
    const uint32_t boffs = (uint32_t)((n0 + ((lane >> 4) & 1) * 8 + (lane & 7)) * LDS_ROW
                                      + ((lane >> 3) & 1) * 16);

    float acc[2][8][4];
    #pragma unroll
    for (int mi = 0; mi < 2; mi++)
        #pragma unroll
        for (int nj = 0; nj < 8; nj++)
            #pragma unroll
            for (int t = 0; t < 4; t++) acc[mi][nj][t] = 0.f;

    auto load_stage = [&](int s) {
        const int b = s & 1;
        const long k0 = (long)s << 6;
        #pragma unroll
        for (int i = 0; i < 4; i++) {
            const int r = lr + i * 32;
            uint32_t d = smb + (uint32_t)(b * STGBUF + r * LDS_ROW + cch * 16);
            long go = (long)(rowBase + r) * K + k0 + cch * 8;
            cp_async16(d + OFF_A, Ahi + go, 16);
            long gb = (long)(colBase + r) * K + k0 + cch * 8;
            cp_async16(d + OFF_B, Bm + gb, 16);
        }
        CP_COMMIT();
    };

    load_stage(0);
    for (int s = 0; s < NS; ++s) {
        if (s + 1 < NS) {
            load_stage(s + 1);
            CP_WAIT(1);
        } else {
            CP_WAIT(0);
        }
        __syncthreads();
        gemm_stage_compute(smb + (s & 1) * STGBUF, aoffs, boffs, acc);
        __syncthreads();
    }

    // Epilogue: fp32 + bias + residual
    const int g = lane >> 2, tig = lane & 3;
    const float* bias = args.bias;
    const float* resid = args.resid;
    #pragma unroll
    for (int mi = 0; mi < 2; mi++) {
        #pragma unroll
        for (int nj = 0; nj < 8; nj++) {
            const int r0 = rowBase + m0 + mi * 16 + g;
            const int col = colBase + n0 + nj * 8 + tig * 2;
            float2 v0 = make_float2(acc[mi][nj][0], acc[mi][nj][1]);
            float2 v1 = make_float2(acc[mi][nj][2], acc[mi][nj][3]);
            const float2 bi = *(const float2*)(bias + col);
            v0.x += bi.x; v0.y += bi.y;
            v1.x += bi.x; v1.y += bi.y;
            const float2 rr0 = *(const float2*)(resid + (long)r0 * ldc + col);
            v0.x += rr0.x; v0.y += rr0.y;
            const float2 rr1 = *(const float2*)(resid + (long)(r0 + 8) * ldc + col);
            v1.x += rr1.x; v1.y += rr1.y;
            *(float2*)(args.C + (long)r0 * ldc + col)       = v0;
            *(float2*)(args.C + (long)(r0 + 8) * ldc + col) = v1;
        }
    }
}

// Sum NSPLIT split-K partials -> kv fp16.
__global__ __launch_bounds__(256)
void reduce_split_kv(const float* __restrict__ part, __half* __restrict__ hi)
{
    const long n4 = PART_STRIDE / 4;
    long i = (long)blockIdx.x * 256 + threadIdx.x;
    if (i >= n4) return;
    const float4* p4 = (const float4*)part;
    float4 s = p4[i];
    #pragma unroll
    for (int k = 1; k < NSPLIT; k++) {
        float4 t = p4[i + (long)k * n4];
        s.x += t.x; s.y += t.y; s.z += t.z; s.w += t.w;
    }
    ((uint2*)hi)[i] = make_uint2(pack_half2(s.x, s.y), pack_half2(s.z, s.w));
}

// ============================================================================
// HMMA flash attention: CTA = 128 q-rows x 96 keys (77 text + pad + 4 ip @80).
// 8 warps, warp = 16 rows. Pure fp16. V [key][dim] + ldsm.trans.
// Writes hs as fp16.
// ============================================================================
#define AROW 144
#define KROW 144
#define OFF_Q  0
#define OFF_K  (128 * AROW)                 // 18432
#define OFF_V  (OFF_K + 96 * KROW)          // 32256
#define SMEM_ATTN (OFF_V + 96 * KROW)       // 46080

__global__ __launch_bounds__(256)
void attn_mma(const __half* __restrict__ qhi,
              const __half* __restrict__ kv,
              __half* __restrict__ ohi)
{
    extern __shared__ __align__(16) char smx[];
    const uint32_t smb = smem_to_u32(smx);
    const int tid = threadIdx.x;
    const int b = blockIdx.z, h = blockIdx.y;
    const int rowBase = blockIdx.x * 128;
    const long SLAB = (long)NB * TXT * HIDDEN;

    // Q tile: 128 rows x 64 dims
    #pragma unroll
    for (int i = 0; i < 4; i++) {
        int idx = tid + i * 256;
        int r = idx >> 3, c = idx & 7;
        long src = ((long)b * SQ + rowBase + r) * HIDDEN + h * 64 + c * 8;
        cp_async16(smb + OFF_Q + (uint32_t)(r * AROW + c * 16), qhi + src, 16);
    }
    // K tile: rows 0-76 text K, 80-83 ipK, rest zero
    #pragma unroll
    for (int i = 0; i < 3; i++) {
        int idx = tid + i * 256;
        int r = idx >> 3, c = idx & 7;
        int bytes = 0;
        long src = 0;
        if (r < TXT) {
            bytes = 16;
            src = (long)b * TXT * HIDDEN + (long)r * HIDDEN + h * 64 + c * 8;
        } else if (r >= 80 && r < 80 + NTOK) {
            bytes = 16;
            src = 2 * SLAB + (long)b * TXT * HIDDEN + (long)(r - 80) * HIDDEN + h * 64 + c * 8;
        }
        cp_async16(smb + OFF_K + (uint32_t)(r * KROW + c * 16), kv + src, bytes);
    }
    // V tile: rows 0-76 text V, 80-83 ipV, [key][dim]
    #pragma unroll
    for (int i = 0; i < 3; i++) {
        int idx = tid + i * 256;
        int r = idx >> 3, c = idx & 7;
        int bytes = 0;
        long src = 0;
        if (r < TXT) {
            bytes = 16;
            src = SLAB + (long)b * TXT * HIDDEN + (long)r * HIDDEN + h * 64 + c * 8;
        } else if (r >= 80 && r < 80 + NTOK) {
            bytes = 16;
            src = 3 * SLAB + (long)b * TXT * HIDDEN + (long)(r - 80) * HIDDEN + h * 64 + c * 8;
        }
        cp_async16(smb + OFF_V + (uint32_t)(r * KROW + c * 16), kv + src, bytes);
    }
    CP_COMMIT();
    CP_WAIT(0);
    __syncthreads();

    const int warp = tid >> 5, lane = tid & 31;
    const int m0 = warp * 16;
    const int tig = lane & 3;
    const uint32_t aoffs = smb + OFF_Q + (uint32_t)((m0 + (lane & 15)) * AROW + (lane >> 4) * 16);
    const uint32_t kbase = smb + OFF_K
        + (uint32_t)((((lane >> 4) & 1) * 8 + (lane & 7)) * KROW + ((lane >> 3) & 1) * 16);

    // S = Q K^T (12 n-tiles of 8 keys = 96)
    float s[12][4];
    #pragma unroll
    for (int j = 0; j < 12; j++)
        #pragma unroll
        for (int e = 0; e < 4; e++) s[j][e] = 0.f;

    #pragma unroll
    for (int ks = 0; ks < 4; ks++) {
        uint32_t Qh[4];
        ldsm_x4(Qh, aoffs + ks * 32);
        #pragma unroll
        for (int t = 0; t < 6; t++) {
            uint32_t Bh[4];
            ldsm_x4(Bh, kbase + t * 16 * KROW + ks * 32);
            mma16816(s[2 * t + 0], Qh, Bh[0], Bh[1]);
            mma16816(s[2 * t + 1], Qh, Bh[2], Bh[3]);
        }
    }

    // scale + mask + dual softmax
    const bool ipOn = (b & 1);
    float mx[2]  = {-1e30f, -1e30f};
    float mx2[2] = {-1e30f, -1e30f};
    #pragma unroll
    for (int j = 0; j < 10; j++)
        #pragma unroll
        for (int e = 0; e < 4; e++) {
            int col = j * 8 + tig * 2 + (e & 1);
            float v = s[j][e] * 0.125f;
            s[j][e] = (col < TXT) ? v : -1e30f;
            mx[e >> 1] = fmaxf(mx[e >> 1], s[j][e]);
        }
    #pragma unroll
    for (int j = 10; j < 12; j++)
        #pragma unroll
        for (int e = 0; e < 4; e++) {
            int col = j * 8 + tig * 2 + (e & 1);
            float v = s[j][e] * 0.125f;
            s[j][e] = (col >= 80 && col < 80 + NTOK) ? v : -1e30f;
            mx2[e >> 1] = fmaxf(mx2[e >> 1], s[j][e]);
        }
    #pragma unroll
    for (int off = 1; off <= 2; off <<= 1) {
        mx[0]  = fmaxf(mx[0],  __shfl_xor_sync(0xffffffffu, mx[0],  off));
        mx[1]  = fmaxf(mx[1],  __shfl_xor_sync(0xffffffffu, mx[1],  off));
        mx2[0] = fmaxf(mx2[0], __shfl_xor_sync(0xffffffffu, mx2[0], off));
        mx2[1] = fmaxf(mx2[1], __shfl_xor_sync(0xffffffffu, mx2[1], off));
    }
    float l[2] = {0.f, 0.f}, l2[2] = {0.f, 0.f};
    #pragma unroll
    for (int j = 0; j < 10; j++)
        #pragma unroll
        for (int e = 0; e < 4; e++) {
            float p = __expf(s[j][e] - mx[e >> 1]);
            s[j][e] = p;
            l[e >> 1] += p;
        }
    #pragma unroll
    for (int j = 10; j < 12; j++)
        #pragma unroll
        for (int e = 0; e < 4; e++) {
            float p = __expf(s[j][e] - mx2[e >> 1]);
            s[j][e] = p;
            l2[e >> 1] += p;
        }
    #pragma unroll
    for (int off = 1; off <= 2; off <<= 1) {
        l[0]  += __shfl_xor_sync(0xffffffffu, l[0],  off);
        l[1]  += __shfl_xor_sync(0xffffffffu, l[1],  off);
        l2[0] += __shfl_xor_sync(0xffffffffu, l2[0], off);
        l2[1] += __shfl_xor_sync(0xffffffffu, l2[1], off);
    }
    float inv[2], inv2[2];
    inv[0] = 1.f / l[0];
    inv[1] = 1.f / l[1];
    inv2[0] = ipOn ? 1.f / l2[0] : 0.f;
    inv2[1] = ipOn ? 1.f / l2[1] : 0.f;
    #pragma unroll
    for (int j = 0; j < 10; j++)
        #pragma unroll
        for (int e = 0; e < 4; e++) s[j][e] *= inv[e >> 1];
    #pragma unroll
    for (int j = 10; j < 12; j++)
        #pragma unroll
        for (int e = 0; e < 4; e++) s[j][e] *= inv2[e >> 1];

    // PV via ldsm.trans on V[key][dim]
    const uint32_t vtbase = smb + OFF_V
        + (uint32_t)((((lane >> 3) & 1) * 8 + (lane & 7)) * KROW + ((lane >> 4) & 1) * 16);
    float out[8][4];
    #pragma unroll
    for (int d = 0; d < 8; d++)
        #pragma unroll
        for (int e = 0; e < 4; e++) out[d][e] = 0.f;

    #pragma unroll
    for (int kk = 0; kk < 6; kk++) {
        uint32_t ah[4];
        #pragma unroll
        for (int r = 0; r < 4; r++) {
            const int t = 2 * kk + (r >> 1);
            const int pi = (r & 1) * 2;
            ah[r] = pack_half2(s[t][pi], s[t][pi + 1]);
        }
        #pragma unroll
        for (int d = 0; d < 4; d++) {
            uint32_t Vh[4];
            ldsm_x4_t(Vh, vtbase + kk * 16 * KROW + d * 32);
            mma16816(out[2 * d + 0], ah, Vh[0], Vh[1]);
            mma16816(out[2 * d + 1], ah, Vh[2], Vh[3]);
        }
    }

    // write hs fp16
    const int g = lane >> 2;
    const long row0 = (long)b * SQ + rowBase + m0 + g;
    #pragma unroll
    for (int d = 0; d < 8; d++) {
        const int col = h * 64 + d * 8 + tig * 2;
        #pragma unroll
        for (int rr = 0; rr < 2; rr++) {
            long o = (row0 + rr * 8) * HIDDEN + col;
            *(uint32_t*)(ohi + o) = pack_half2(out[d][rr * 2 + 0], out[d][rr * 2 + 1]);
        }
    }
}

// ============================================================================
// Launcher
// ============================================================================
extern "C" void kernel_launch(void* const* d_in, const int* in_sizes, int n_in,
                              void* d_out, int out_size)
{
    const float* hidden = (const float*)d_in[0];
    const float* enc    = (const float*)d_in[1];
    const float* Wq     = (const float*)d_in[2];
    const float* Wk     = (const float*)d_in[3];
    const float* Wv     = (const float*)d_in[4];
    const float* Wk_ip  = (const float*)d_in[5];
    const float* Wv_ip  = (const float*)d_in[6];
    const float* Wout   = (const float*)d_in[7];
    const float* b_out  = (const float*)d_in[8];
    float* out = (float*)d_out;

    static bool attr_set = false;
    if (!attr_set) {
        cudaFuncSetAttribute(hmma_gemm, cudaFuncAttributeMaxDynamicSharedMemorySize, SMEM_TOT);
        cudaFuncSetAttribute(hmma_gemm_qkv, cudaFuncAttributeMaxDynamicSharedMemorySize, SMEM_TOT);
        cudaFuncSetAttribute(attn_mma, cudaFuncAttributeMaxDynamicSharedMemorySize, SMEM_ATTN);
        attr_set = true;
    }

    __half *ahi, *qhi, *ehi, *wq, *wt, *wo, *kv;
    float* pbuf;
    cudaGetSymbolAddress((void**)&ahi, g_ahi);
    cudaGetSymbolAddress((void**)&qhi, g_qhi);
    cudaGetSymbolAddress((void**)&ehi, g_ehi);
    cudaGetSymbolAddress((void**)&wq,  g_wqT);
    cudaGetSymbolAddress((void**)&wt,  g_wT);
    cudaGetSymbolAddress((void**)&wo,  g_woutT);
    cudaGetSymbolAddress((void**)&kv,  g_kv);
    cudaGetSymbolAddress((void**)&pbuf, g_part);

    const int M_big = NB * SQ;  // 16384
    const long WSLAB = (long)HIDDEN * CROSS;

    // 1) merged prep: transposes first, then converts
    {
        PrepArgs p;
        p.wsrc[0] = Wq;    p.wdst[0] = wq;             p.K[0] = HIDDEN;
        p.wsrc[1] = Wk;    p.wdst[1] = wt + 0 * WSLAB; p.K[1] = CROSS;
        p.wsrc[2] = Wv;    p.wdst[2] = wt + 1 * WSLAB; p.K[2] = CROSS;
        p.wsrc[3] = Wk_ip; p.wdst[3] = wt + 2 * WSLAB; p.K[3] = CROSS;
        p.wsrc[4] = Wv_ip; p.wdst[4] = wt + 3 * WSLAB; p.K[4] = CROSS;
        p.wsrc[5] = Wout;  p.wdst[5] = wo;             p.K[5] = HIDDEN;
        p.hidden = hidden; p.enc = enc;
        p.ahi = ahi; p.ehi = ehi;
        prep_all<<<NT_BLK + NE_BLK + NH_BLK, 256>>>(p);
    }

    // 2) merged Q projection + packed split-K kv projections (1920 CTAs)
    {
        QKVArgs a;
        a.ahi = ahi; a.ehi = ehi;
        a.wq = wq; a.wt = wt;
        a.qhi = qhi; a.pbuf = pbuf;
        hmma_gemm_qkv<<<1280 + NSPLIT * 80, 256, SMEM_TOT>>>(a);
    }

    // 3) reduce split-K partials -> kv fp16
    {
        long n4 = PART_STRIDE / 4;
        reduce_split_kv<<<(int)((n4 + 255) / 256), 256>>>(pbuf, kv);
    }

    // 4) HMMA attention -> hs fp16 (reuses g_ahi)
    attn_mma<<<dim3(SQ / 128, NHEADS, NB), 256, SMEM_ATTN>>>(qhi, kv, ahi);

    // 5) out = hs @ Wout + b_out + residual (fp32)
    {
        GemmArgs a = {ahi, wo, out, HIDDEN, HIDDEN, b_out, hidden};
        hmma_gemm<<<dim3(HIDDEN / 128, M_big / 128, 1), 256, SMEM_TOT>>>(a);
    }
}

// round 16
// speedup vs baseline: 1.1726x; 1.0085x over previous
#include <cuda_runtime.h>
#include <cuda_fp16.h>
#include <cstdint>

#define NHEADS 20
#define HEAD_DIM 64
#define HIDDEN 1280
#define CROSS 2048
#define NB 4
#define SQ 4096
#define TXT 77
#define NTOK 4
#define ENC (TXT + NTOK)

// ============================================================================
// PTX helpers (baseline-family only: mma.sync / ldmatrix / cp.async)
// ============================================================================
__device__ __forceinline__ uint32_t smem_to_u32(const void* smem_ptr) {
    uint32_t addr;
    asm("{ .reg .u64 tmp; cvta.to.shared.u64 tmp, %1; cvt.u32.u64 %0, tmp; }"
        : "=r"(addr) : "l"(smem_ptr));
    return addr;
}

__device__ __forceinline__ void cp_async16(uint32_t dst, const void* src, int bytes) {
    asm volatile("cp.async.cg.shared.global [%0], [%1], 16, %2;"
                 :: "r"(dst), "l"(src), "r"(bytes));
}
#define CP_COMMIT() asm volatile("cp.async.commit_group;" ::: "memory")
#define CP_WAIT(N)  asm volatile("cp.async.wait_group %0;" :: "n"(N) : "memory")

__device__ __forceinline__ void ldsm_x4(uint32_t* r, uint32_t a) {
    asm volatile("ldmatrix.sync.aligned.m8n8.x4.shared.b16 {%0,%1,%2,%3}, [%4];"
                 : "=r"(r[0]), "=r"(r[1]), "=r"(r[2]), "=r"(r[3]) : "r"(a));
}

__device__ __forceinline__ void ldsm_x4_t(uint32_t* r, uint32_t a) {
    asm volatile("ldmatrix.sync.aligned.m8n8.x4.trans.shared.b16 {%0,%1,%2,%3}, [%4];"
                 : "=r"(r[0]), "=r"(r[1]), "=r"(r[2]), "=r"(r[3]) : "r"(a));
}

// f16 x f16 -> f32 MMA
__device__ __forceinline__ void mma16816(float* c, const uint32_t* a,
                                         uint32_t b0, uint32_t b1) {
    asm volatile(
        "mma.sync.aligned.m16n8k16.row.col.f32.f16.f16.f32 "
        "{%0,%1,%2,%3},{%4,%5,%6,%7},{%8,%9},{%0,%1,%2,%3};"
        : "+f"(c[0]), "+f"(c[1]), "+f"(c[2]), "+f"(c[3])
        : "r"(a[0]), "r"(a[1]), "r"(a[2]), "r"(a[3]), "r"(b0), "r"(b1));
}

__device__ __forceinline__ uint32_t pack_half2(float a, float b) {
    __half2 t;
    t.x = __float2half(a);
    t.y = __float2half(b);
    return *reinterpret_cast<uint32_t*>(&t);
}

// ============================================================================
// Scratch (static device allocations)
// ============================================================================
#define PART_STRIDE ((long)16 * TXT * HIDDEN)   // floats per split-K partial
#define NSPLIT 4

__device__ __half g_ahi[NB * SQ * HIDDEN];            // hidden-hi, then hs-hi
__device__ __half g_qhi[NB * SQ * HIDDEN];
__device__ __half g_ehi[NB * ENC * CROSS];
__device__ __half g_wq[HIDDEN * HIDDEN];              // [K][N] row-major fp16
__device__ __half g_w4[4 * HIDDEN * CROSS];           // wk, wv, wkip, wvip [K][N]
__device__ __half g_wo[HIDDEN * HIDDEN];
__device__ __half g_kv[4 * NB * TXT * HIDDEN];        // k,v,ipk,ipv
__device__ float g_part[NSPLIT * 16 * TXT * HIDDEN];  // split-K partials

// ============================================================================
// Merged prep: pure fp32 -> fp16 converts of 6 weights + 2 activations.
// All segment sizes are exact multiples of 1024 floats -> no guards.
// ============================================================================
struct PrepArgs {
    const float* src[8];
    __half* dst[8];
    int blkOff[9];
};

__global__ __launch_bounds__(256)
void prep_all(PrepArgs p)
{
    const int bid = blockIdx.x;
    int s = 0;
    #pragma unroll
    for (int k = 1; k < 8; k++)
        if (bid >= p.blkOff[k]) s = k;
    const long i = (long)(bid - p.blkOff[s]) * 256 + threadIdx.x;
    float4 x = ((const float4*)p.src[s])[i];
    ((uint2*)p.dst[s])[i] = make_uint2(pack_half2(x.x, x.y), pack_half2(x.z, x.w));
}

// ============================================================================
// Shared GEMM pieces: CTA 128x128x64 (BK=64), 8 warps, warp 32x64, cp.async
// double buffer, pure fp16. A row-major (ldsm), B row-major [K][N] (ldsm.trans).
// A rows 144B (128 data + 16 pad); B rows 272B (256 data + 16 pad).
// Both conflict-free: row*stride mod 128 = row*16.
// ============================================================================
#define LDSA_ROW 144
#define LDSB_ROW 272
#define OFF_A   0
#define OFF_B   18432                 // 128 * 144
#define STGBUF  (18432 + 64 * 272)    // 35840
#define SMEM_TOT (2 * STGBUF)         // 71680

// Interleaved per-accumulator compute (do NOT burst-reorder; see R8).
// Per-accumulator k-order identical to R15 -> bitwise-identical results.
__device__ __forceinline__ void gemm_stage_compute(
    uint32_t base, uint32_t aoffs, uint32_t boffs, float acc[2][8][4])
{
    const uint32_t aA = base + OFF_A;
    const uint32_t bB = base + OFF_B;
    #pragma unroll
    for (int ks = 0; ks < 4; ks++) {
        uint32_t Ah[2][4];
        #pragma unroll
        for (int mi = 0; mi < 2; mi++)
            ldsm_x4(Ah[mi], aA + aoffs + mi * 16 * LDSA_ROW + ks * 32);
        #pragma unroll
        for (int nq = 0; nq < 4; nq++) {
            uint32_t Bh[4];
            ldsm_x4_t(Bh, bB + boffs + ks * 16 * LDSB_ROW + nq * 32);
            #pragma unroll
            for (int mi = 0; mi < 2; mi++) {
                mma16816(acc[mi][nq * 2 + 0], Ah[mi], Bh[0], Bh[1]);
                mma16816(acc[mi][nq * 2 + 1], Ah[mi], Bh[2], Bh[3]);
            }
        }
    }
}

// kv packed-row map: parts 0-2 text K (4x77 rows), 3-5 text V, 6 ipK (16), 7 ipV.
__device__ __forceinline__ bool kv_map(int part, int r, long& aRow, long& cRow)
{
    aRow = 0; cRow = 0;
    if (part < 6) {
        int R = (part % 3) * 128 + r;
        if (R >= 4 * TXT) return false;
        int batch = R / TXT, rr = R - batch * TXT;
        aRow = (long)batch * ENC + rr;
        cRow = (long)(((part < 3 ? 0 : 1) * 4 + batch) * TXT + rr);
        return true;
    } else {
        if (r >= 16) return false;
        int batch = r >> 2, rr = r & 3;
        aRow = (long)batch * ENC + TXT + rr;
        cRow = (long)(((part == 6 ? 2 : 3) * 4 + batch) * TXT + rr);
        return true;
    }
}

// ============================================================================
// Merged Q-projection + packed split-K kv-projection GEMM (BK=64).
// 1-D grid of 1600 CTAs: bid < 1280 -> Q tile (20 stages),
// bid >= 1280 -> kv tile (8 stages, 4 K-splits, backfills Q tail wave).
// ============================================================================
struct QKVArgs {
    const __half *ahi, *ehi;
    const __half *wq, *w4;
    __half *qhi;
    float* pbuf;
};

__global__ __launch_bounds__(256, 2)
void hmma_gemm_qkv(QKVArgs args)
{
    extern __shared__ __align__(16) char smx[];
    const uint32_t smb = smem_to_u32(smx);
    const int tid = threadIdx.x;
    const int bid = blockIdx.x;
    const bool isQ = bid < 1280;

    const int lr  = tid >> 3;      // A loader: rows lr + {0,32,64,96}
    const int cch = tid & 7;       // A col chunk (8 x 16B)
    const int br  = tid >> 4;      // B loader: rows br + {0,16,32,48}
    const int bcc = tid & 15;      // B col chunk (16 x 16B)

    const __half *Ahi, *Bm;
    int K, NS, kBase, colBase, rowBase = 0, part = 0, split = 0;
    int aRow[4];
    int aBytes[4];

    if (isQ) {
        rowBase = (bid / 10) * 128;
        colBase = (bid % 10) * 128;
        Ahi = args.ahi;
        Bm = args.wq;
        K = HIDDEN; NS = 20; kBase = 0;
        #pragma unroll
        for (int i = 0; i < 4; i++) {
            aRow[i] = rowBase + lr + i * 32;
            aBytes[i] = 16;
        }
    } else {
        const int t = bid - 1280;
        colBase = (t % 10) * 128;
        part = (t / 10) & 7;
        split = t / 80;            // 0..3
        const int gemm = part < 3 ? 0 : (part < 6 ? 1 : (part == 6 ? 2 : 3));
        Ahi = args.ehi;
        Bm = args.w4 + (long)gemm * HIDDEN * CROSS;
        K = CROSS; NS = 8; kBase = split * 512;
        #pragma unroll
        for (int i = 0; i < 4; i++) {
            long ar, cr;
            aBytes[i] = kv_map(part, lr + i * 32, ar, cr) ? 16 : 0;
            aRow[i] = (int)ar;
        }
    }

    const int warp = tid >> 5, lane = tid & 31;
    const int wm = warp >> 1, wn = warp & 1;
    const int m0 = wm * 32, n0 = wn * 64;

    const uint32_t aoffs = (uint32_t)((m0 + (lane & 15)) * LDSA_ROW + (lane >> 4) * 16);
    const uint32_t boffs = (uint32_t)(((((lane >> 3) & 1) * 8 + (lane & 7)) * LDSB_ROW)
                                      + ((lane >> 4) & 1) * 16 + n0 * 2);

    float acc[2][8][4];
    #pragma unroll
    for (int mi = 0; mi < 2; mi++)
        #pragma unroll
        for (int nj = 0; nj < 8; nj++)
            #pragma unroll
            for (int t = 0; t < 4; t++) acc[mi][nj][t] = 0.f;

    auto load_stage = [&](int s) {
        const int b = s & 1;
        const int k0 = kBase + (s << 6);
        #pragma unroll
        for (int i = 0; i < 4; i++) {
            const int r = lr + i * 32;
            uint32_t d = smb + (uint32_t)(b * STGBUF + OFF_A + r * LDSA_ROW + cch * 16);
            long go = (long)aRow[i] * K + k0 + cch * 8;
            cp_async16(d, Ahi + go, aBytes[i]);
        }
        #pragma unroll
        for (int i = 0; i < 4; i++) {
            const int r = br + i * 16;
            uint32_t d = smb + (uint32_t)(b * STGBUF + OFF_B + r * LDSB_ROW + bcc * 16);
            long gb = (long)(k0 + r) * HIDDEN + colBase + bcc * 8;
            cp_async16(d, Bm + gb, 16);
        }
        CP_COMMIT();
    };

    load_stage(0);
    for (int s = 0; s < NS; ++s) {
        if (s + 1 < NS) {
            load_stage(s + 1);
            CP_WAIT(1);
        } else {
            CP_WAIT(0);
        }
        __syncthreads();
        gemm_stage_compute(smb + (s & 1) * STGBUF, aoffs, boffs, acc);
        __syncthreads();
    }

    // Epilogue
    const int g = lane >> 2, tig = lane & 3;
    if (isQ) {
        #pragma unroll
        for (int mi = 0; mi < 2; mi++) {
            #pragma unroll
            for (int nj = 0; nj < 8; nj++) {
                const int r0 = rowBase + m0 + mi * 16 + g;
                const int col = colBase + n0 + nj * 8 + tig * 2;
                #pragma unroll
                for (int rr = 0; rr < 2; rr++) {
                    long o = (long)(r0 + rr * 8) * HIDDEN + col;
                    *(uint32_t*)(args.qhi + o) =
                        pack_half2(acc[mi][nj][rr * 2 + 0], acc[mi][nj][rr * 2 + 1]);
                }
            }
        }
    } else {
        float* pout = args.pbuf + (long)split * PART_STRIDE;
        #pragma unroll
        for (int mi = 0; mi < 2; mi++) {
            #pragma unroll
            for (int nj = 0; nj < 8; nj++) {
                const int r0 = m0 + mi * 16 + g;
                const int col = colBase + n0 + nj * 8 + tig * 2;
                long aR, cR;
                if (kv_map(part, r0, aR, cR))
                    *(float2*)(pout + cR * HIDDEN + col) =
                        make_float2(acc[mi][nj][0], acc[mi][nj][1]);
                if (kv_map(part, r0 + 8, aR, cR))
                    *(float2*)(pout + cR * HIDDEN + col) =
                        make_float2(acc[mi][nj][2], acc[mi][nj][3]);
            }
        }
    }
}

// ============================================================================
// Out-projection GEMM (BK=64, trans-B, pure fp16, fused bias+resid).
// ============================================================================
struct GemmArgs {
    const __half *Ahi, *Bm;
    float* C;
    int K, ldc;
    const float *bias, *resid;
};

__global__ __launch_bounds__(256, 2)
void hmma_gemm(GemmArgs args)
{
    extern __shared__ __align__(16) char smx[];
    const uint32_t smb = smem_to_u32(smx);
    const int tid = threadIdx.x;

    const __half* Ahi = args.Ahi;
    const __half* Bm = args.Bm;
    const int K = args.K, ldc = args.ldc;

    const int rowBase = blockIdx.y * 128;
    const int colBase = blockIdx.x * 128;
    const int NS = K >> 6;
    const int lr  = tid >> 3;
    const int cch = tid & 7;
    const int br  = tid >> 4;
    const int bcc = tid & 15;

    const int warp = tid >> 5, lane = tid & 31;
    const int wm = warp >> 1, wn = warp & 1;
    const int m0 = wm * 32, n0 = wn * 64;

    const uint32_t aoffs = (uint32_t)((m0 + (lane & 15)) * LDSA_ROW + (lane >> 4) * 16);
    const uint32_t boffs = (uint32_t)(((((lane >> 3) & 1) * 8 + (lane & 7)) * LDSB_ROW)
                                      + ((lane >> 4) & 1) * 16 + n0 * 2);

    float acc[2][8][4];
    #pragma unroll
    for (int mi = 0; mi < 2; mi++)
        #pragma unroll
        for (int nj = 0; nj < 8; nj++)
            #pragma unroll
            for (int t = 0; t < 4; t++) acc[mi][nj][t] = 0.f;

    auto load_stage = [&](int s) {
        const int b = s & 1;
        const int k0 = s << 6;
        #pragma unroll
        for (int i = 0; i < 4; i++) {
            const int r = lr + i * 32;
            uint32_t d = smb + (uint32_t)(b * STGBUF + OFF_A + r * LDSA_ROW + cch * 16);
            long go = (long)(rowBase + r) * K + k0 + cch * 8;
            cp_async16(d, Ahi + go, 16);
        }
        #pragma unroll
        for (int i = 0; i < 4; i++) {
            const int r = br + i * 16;
            uint32_t d = smb + (uint32_t)(b * STGBUF + OFF_B + r * LDSB_ROW + bcc * 16);
            long gb = (long)(k0 + r) * HIDDEN + colBase + bcc * 8;
            cp_async16(d, Bm + gb, 16);
        }
        CP_COMMIT();
    };

    load_stage(0);
    for (int s = 0; s < NS; ++s) {
        if (s + 1 < NS) {
            load_stage(s + 1);
            CP_WAIT(1);
        } else {
            CP_WAIT(0);
        }
        __syncthreads();
        gemm_stage_compute(smb + (s & 1) * STGBUF, aoffs, boffs, acc);
        __syncthreads();
    }

    // Epilogue: fp32 + bias + residual
    const int g = lane >> 2, tig = lane & 3;
    const float* bias = args.bias;
    const float* resid = args.resid;
    #pragma unroll
    for (int mi = 0; mi < 2; mi++) {
        #pragma unroll
        for (int nj = 0; nj < 8; nj++) {
            const int r0 = rowBase + m0 + mi * 16 + g;
            const int col = colBase + n0 + nj * 8 + tig * 2;
            float2 v0 = make_float2(acc[mi][nj][0], acc[mi][nj][1]);
            float2 v1 = make_float2(acc[mi][nj][2], acc[mi][nj][3]);
            const float2 bi = *(const float2*)(bias + col);
            v0.x += bi.x; v0.y += bi.y;
            v1.x += bi.x; v1.y += bi.y;
            const float2 rr0 = *(const float2*)(resid + (long)r0 * ldc + col);
            v0.x += rr0.x; v0.y += rr0.y;
            const float2 rr1 = *(const float2*)(resid + (long)(r0 + 8) * ldc + col);
            v1.x += rr1.x; v1.y += rr1.y;
            *(float2*)(args.C + (long)r0 * ldc + col)       = v0;
            *(float2*)(args.C + (long)(r0 + 8) * ldc + col) = v1;
        }
    }
}

// Sum NSPLIT split-K partials -> kv fp16.
__global__ __launch_bounds__(256)
void reduce_split_kv(const float* __restrict__ part, __half* __restrict__ hi)
{
    const long n4 = PART_STRIDE / 4;
    long i = (long)blockIdx.x * 256 + threadIdx.x;
    if (i >= n4) return;
    const float4* p4 = (const float4*)part;
    float4 s = p4[i];
    #pragma unroll
    for (int k = 1; k < NSPLIT; k++) {
        float4 t = p4[i + (long)k * n4];
        s.x += t.x; s.y += t.y; s.z += t.z; s.w += t.w;
    }
    ((uint2*)hi)[i] = make_uint2(pack_half2(s.x, s.y), pack_half2(s.z, s.w));
}

// ============================================================================
// HMMA flash attention: CTA = 128 q-rows x 96 keys (77 text + pad + 4 ip @80).
// 8 warps, warp = 16 rows. Pure fp16. V [key][dim] + ldsm.trans.
// Writes hs as fp16.
// ============================================================================
#define AROW 144
#define KROW 144
#define OFF_Q  0
#define OFF_K  (128 * AROW)                 // 18432
#define OFF_V  (OFF_K + 96 * KROW)          // 32256
#define SMEM_ATTN (OFF_V + 96 * KROW)       // 46080

__global__ __launch_bounds__(256)
void attn_mma(const __half* __restrict__ qhi,
              const __half* __restrict__ kv,
              __half* __restrict__ ohi)
{
    extern __shared__ __align__(16) char smx[];
    const uint32_t smb = smem_to_u32(smx);
    const int tid = threadIdx.x;
    const int b = blockIdx.z, h = blockIdx.y;
    const int rowBase = blockIdx.x * 128;
    const long SLAB = (long)NB * TXT * HIDDEN;

    // Q tile: 128 rows x 64 dims
    #pragma unroll
    for (int i = 0; i < 4; i++) {
        int idx = tid + i * 256;
        int r = idx >> 3, c = idx & 7;
        long src = ((long)b * SQ + rowBase + r) * HIDDEN + h * 64 + c * 8;
        cp_async16(smb + OFF_Q + (uint32_t)(r * AROW + c * 16), qhi + src, 16);
    }
    // K tile: rows 0-76 text K, 80-83 ipK, rest zero
    #pragma unroll
    for (int i = 0; i < 3; i++) {
        int idx = tid + i * 256;
        int r = idx >> 3, c = idx & 7;
        int bytes = 0;
        long src = 0;
        if (r < TXT) {
            bytes = 16;
            src = (long)b * TXT * HIDDEN + (long)r * HIDDEN + h * 64 + c * 8;
        } else if (r >= 80 && r < 80 + NTOK) {
            bytes = 16;
            src = 2 * SLAB + (long)b * TXT * HIDDEN + (long)(r - 80) * HIDDEN + h * 64 + c * 8;
        }
        cp_async16(smb + OFF_K + (uint32_t)(r * KROW + c * 16), kv + src, bytes);
    }
    // V tile: rows 0-76 text V, 80-83 ipV, [key][dim]
    #pragma unroll
    for (int i = 0; i < 3; i++) {
        int idx = tid + i * 256;
        int r = idx >> 3, c = idx & 7;
        int bytes = 0;
        long src = 0;
        if (r < TXT) {
            bytes = 16;
            src = SLAB + (long)b * TXT * HIDDEN + (long)r * HIDDEN + h * 64 + c * 8;
        } else if (r >= 80 && r < 80 + NTOK) {
            bytes = 16;
            src = 3 * SLAB + (long)b * TXT * HIDDEN + (long)(r - 80) * HIDDEN + h * 64 + c * 8;
        }
        cp_async16(smb + OFF_V + (uint32_t)(r * KROW + c * 16), kv + src, bytes);
    }
    CP_COMMIT();
    CP_WAIT(0);
    __syncthreads();

    const int warp = tid >> 5, lane = tid & 31;
    const int m0 = warp * 16;
    const int tig = lane & 3;
    const uint32_t aoffs = smb + OFF_Q + (uint32_t)((m0 + (lane & 15)) * AROW + (lane >> 4) * 16);
    const uint32_t kbase = smb + OFF_K
        + (uint32_t)((((lane >> 4) & 1) * 8 + (lane & 7)) * KROW + ((lane >> 3) & 1) * 16);

    // S = Q K^T (tiles j=0..10 computed; j=11 is pure padding -> stays 0)
    float s[12][4];
    #pragma unroll
    for (int j = 0; j < 12; j++)
        #pragma unroll
        for (int e = 0; e < 4; e++) s[j][e] = 0.f;

    #pragma unroll
    for (int ks = 0; ks < 4; ks++) {
        uint32_t Qh[4];
        ldsm_x4(Qh, aoffs + ks * 32);
        #pragma unroll
        for (int t = 0; t < 6; t++) {
            uint32_t Bh[4];
            ldsm_x4(Bh, kbase + t * 16 * KROW + ks * 32);
            mma16816(s[2 * t + 0], Qh, Bh[0], Bh[1]);
            if (t < 5) mma16816(s[2 * t + 1], Qh, Bh[2], Bh[3]);
        }
    }

    // scale + mask + dual softmax
    const bool ipOn = (b & 1);
    float mx[2]  = {-1e30f, -1e30f};
    float mx2[2] = {-1e30f, -1e30f};
    #pragma unroll
    for (int j = 0; j < 10; j++)
        #pragma unroll
        for (int e = 0; e < 4; e++) {
            int col = j * 8 + tig * 2 + (e & 1);
            float v = s[j][e] * 0.125f;
            s[j][e] = (col < TXT) ? v : -1e30f;
            mx[e >> 1] = fmaxf(mx[e >> 1], s[j][e]);
        }
    #pragma unroll
    for (int j = 10; j < 12; j++)
        #pragma unroll
        for (int e = 0; e < 4; e++) {
            int col = j * 8 + tig * 2 + (e & 1);
            float v = s[j][e] * 0.125f;
            s[j][e] = (col >= 80 && col < 80 + NTOK) ? v : -1e30f;
            mx2[e >> 1] = fmaxf(mx2[e >> 1], s[j][e]);
        }
    #pragma unroll
    for (int off = 1; off <= 2; off <<= 1) {
        mx[0]  = fmaxf(mx[0],  __shfl_xor_sync(0xffffffffu, mx[0],  off));
        mx[1]  = fmaxf(mx[1],  __shfl_xor_sync(0xffffffffu, mx[1],  off));
        mx2[0] = fmaxf(mx2[0], __shfl_xor_sync(0xffffffffu, mx2[0], off));
        mx2[1] = fmaxf(mx2[1], __shfl_xor_sync(0xffffffffu, mx2[1], off));
    }
    float l[2] = {0.f, 0.f}, l2[2] = {0.f, 0.f};
    #pragma unroll
    for (int j = 0; j < 10; j++)
        #pragma unroll
        for (int e = 0; e < 4; e++) {
            float p = __expf(s[j][e] - mx[e >> 1]);
            s[j][e] = p;
            l[e >> 1] += p;
        }
    #pragma unroll
    for (int j = 10; j < 12; j++)
        #pragma unroll
        for (int e = 0; e < 4; e++) {
            float p = __expf(s[j][e] - mx2[e >> 1]);
            s[j][e] = p;
            l2[e >> 1] += p;
        }
    #pragma unroll
    for (int off = 1; off <= 2; off <<= 1) {
        l[0]  += __shfl_xor_sync(0xffffffffu, l[0],  off);
        l[1]  += __shfl_xor_sync(0xffffffffu, l[1],  off);
        l2[0] += __shfl_xor_sync(0xffffffffu, l2[0], off);
        l2[1] += __shfl_xor_sync(0xffffffffu, l2[1], off);
    }
    float inv[2], inv2[2];
    inv[0] = 1.f / l[0];
    inv[1] = 1.f / l[1];
    inv2[0] = ipOn ? 1.f / l2[0] : 0.f;
    inv2[1] = ipOn ? 1.f / l2[1] : 0.f;
    #pragma unroll
    for (int j = 0; j < 10; j++)
        #pragma unroll
        for (int e = 0; e < 4; e++) s[j][e] *= inv[e >> 1];
    #pragma unroll
    for (int j = 10; j < 12; j++)
        #pragma unroll
        for (int e = 0; e < 4; e++) s[j][e] *= inv2[e >> 1];

    // PV via ldsm.trans on V[key][dim]
    const uint32_t vtbase = smb + OFF_V
        + (uint32_t)((((lane >> 3) & 1) * 8 + (lane & 7)) * KROW + ((lane >> 4) & 1) * 16);
    float out[8][4];
    #pragma unroll
    for (int d = 0; d < 8; d++)
        #pragma unroll
        for (int e = 0; e < 4; e++) out[d][e] = 0.f;

    #pragma unroll
    for (int kk = 0; kk < 6; kk++) {
        uint32_t ah[4];
        #pragma unroll
        for (int r = 0; r < 4; r++) {
            const int t = 2 * kk + (r >> 1);
            const int pi = (r & 1) * 2;
            ah[r] = pack_half2(s[t][pi], s[t][pi + 1]);
        }
        #pragma unroll
        for (int d = 0; d < 4; d++) {
            uint32_t Vh[4];
            ldsm_x4_t(Vh, vtbase + kk * 16 * KROW + d * 32);
            mma16816(out[2 * d + 0], ah, Vh[0], Vh[1]);
            mma16816(out[2 * d + 1], ah, Vh[2], Vh[3]);
        }
    }

    // write hs fp16
    const int g = lane >> 2;
    const long row0 = (long)b * SQ + rowBase + m0 + g;
    #pragma unroll
    for (int d = 0; d < 8; d++) {
        const int col = h * 64 + d * 8 + tig * 2;
        #pragma unroll
        for (int rr = 0; rr < 2; rr++) {
            long o = (row0 + rr * 8) * HIDDEN + col;
            *(uint32_t*)(ohi + o) = pack_half2(out[d][rr * 2 + 0], out[d][rr * 2 + 1]);
        }
    }
}

// ============================================================================
// Launcher
// ============================================================================
extern "C" void kernel_launch(void* const* d_in, const int* in_sizes, int n_in,
                              void* d_out, int out_size)
{
    const float* hidden = (const float*)d_in[0];
    const float* enc    = (const float*)d_in[1];
    const float* Wq     = (const float*)d_in[2];
    const float* Wk     = (const float*)d_in[3];
    const float* Wv     = (const float*)d_in[4];
    const float* Wk_ip  = (const float*)d_in[5];
    const float* Wv_ip  = (const float*)d_in[6];
    const float* Wout   = (const float*)d_in[7];
    const float* b_out  = (const float*)d_in[8];
    float* out = (float*)d_out;

    static bool attr_set = false;
    if (!attr_set) {
        cudaFuncSetAttribute(hmma_gemm, cudaFuncAttributeMaxDynamicSharedMemorySize, SMEM_TOT);
        cudaFuncSetAttribute(hmma_gemm_qkv, cudaFuncAttributeMaxDynamicSharedMemorySize, SMEM_TOT);
        cudaFuncSetAttribute(attn_mma, cudaFuncAttributeMaxDynamicSharedMemorySize, SMEM_ATTN);
        attr_set = true;
    }

    __half *ahi, *qhi, *ehi, *wq, *w4, *wo, *kv;
    float* pbuf;
    cudaGetSymbolAddress((void**)&ahi, g_ahi);
    cudaGetSymbolAddress((void**)&qhi, g_qhi);
    cudaGetSymbolAddress((void**)&ehi, g_ehi);
    cudaGetSymbolAddress((void**)&wq,  g_wq);
    cudaGetSymbolAddress((void**)&w4,  g_w4);
    cudaGetSymbolAddress((void**)&wo,  g_wo);
    cudaGetSymbolAddress((void**)&kv,  g_kv);
    cudaGetSymbolAddress((void**)&pbuf, g_part);

    const int M_big = NB * SQ;  // 16384
    const long WSLAB = (long)HIDDEN * CROSS;

    // 1) merged prep: pure converts (weights kept [K][N]; B uses ldsm.trans)
    {
        // segment block counts: wq 1600, wk/wv/wkip/wvip 2560 each, wout 1600,
        // enc 648, hidden 20480
        PrepArgs p;
        p.src[0] = Wq;    p.dst[0] = wq;
        p.src[1] = Wk;    p.dst[1] = w4 + 0 * WSLAB;
        p.src[2] = Wv;    p.dst[2] = w4 + 1 * WSLAB;
        p.src[3] = Wk_ip; p.dst[3] = w4 + 2 * WSLAB;
        p.src[4] = Wv_ip; p.dst[4] = w4 + 3 * WSLAB;
        p.src[5] = Wout;  p.dst[5] = wo;
        p.src[6] = enc;   p.dst[6] = ehi;
        p.src[7] = hidden; p.dst[7] = ahi;
        p.blkOff[0] = 0;
        p.blkOff[1] = 1600;
        p.blkOff[2] = 1600 + 2560;
        p.blkOff[3] = 1600 + 2 * 2560;
        p.blkOff[4] = 1600 + 3 * 2560;
        p.blkOff[5] = 1600 + 4 * 2560;
        p.blkOff[6] = 3200 + 4 * 2560;
        p.blkOff[7] = 3200 + 4 * 2560 + 648;
        const int total = 3200 + 4 * 2560 + 648 + 20480;   // 34568
        prep_all<<<total, 256>>>(p);
    }

    // 2) merged Q projection + packed split-K kv projections (1600 CTAs)
    {
        QKVArgs a;
        a.ahi = ahi; a.ehi = ehi;
        a.wq = wq; a.w4 = w4;
        a.qhi = qhi; a.pbuf = pbuf;
        hmma_gemm_qkv<<<1280 + NSPLIT * 80, 256, SMEM_TOT>>>(a);
    }

    // 3) reduce split-K partials -> kv fp16
    {
        long n4 = PART_STRIDE / 4;
        reduce_split_kv<<<(int)((n4 + 255) / 256), 256>>>(pbuf, kv);
    }

    // 4) HMMA attention -> hs fp16 (reuses g_ahi)
    attn_mma<<<dim3(SQ / 128, NHEADS, NB), 256, SMEM_ATTN>>>(qhi, kv, ahi);

    // 5) out = hs @ Wout + b_out + residual (fp32)
    {
        GemmArgs a = {ahi, wo, out, HIDDEN, HIDDEN, b_out, hidden};
        hmma_gemm<<<dim3(HIDDEN / 128, M_big / 128, 1), 256, SMEM_TOT>>>(a);
    }
}

// round 17
// speedup vs baseline: 1.1735x; 1.0008x over previous
#include <cuda_runtime.h>
#include <cuda_fp16.h>
#include <cstdint>

#define NHEADS 20
#define HEAD_DIM 64
#define HIDDEN 1280
#define CROSS 2048
#define NB 4
#define SQ 4096
#define TXT 77
#define NTOK 4
#define ENC (TXT + NTOK)

// ============================================================================
// PTX helpers (baseline-family only: mma.sync / ldmatrix / cp.async)
// ============================================================================
__device__ __forceinline__ uint32_t smem_to_u32(const void* smem_ptr) {
    uint32_t addr;
    asm("{ .reg .u64 tmp; cvta.to.shared.u64 tmp, %1; cvt.u32.u64 %0, tmp; }"
        : "=r"(addr) : "l"(smem_ptr));
    return addr;
}

__device__ __forceinline__ void cp_async16(uint32_t dst, const void* src, int bytes) {
    asm volatile("cp.async.cg.shared.global [%0], [%1], 16, %2;"
                 :: "r"(dst), "l"(src), "r"(bytes));
}
#define CP_COMMIT() asm volatile("cp.async.commit_group;" ::: "memory")
#define CP_WAIT(N)  asm volatile("cp.async.wait_group %0;" :: "n"(N) : "memory")

__device__ __forceinline__ void ldsm_x4(uint32_t* r, uint32_t a) {
    asm volatile("ldmatrix.sync.aligned.m8n8.x4.shared.b16 {%0,%1,%2,%3}, [%4];"
                 : "=r"(r[0]), "=r"(r[1]), "=r"(r[2]), "=r"(r[3]) : "r"(a));
}

__device__ __forceinline__ void ldsm_x4_t(uint32_t* r, uint32_t a) {
    asm volatile("ldmatrix.sync.aligned.m8n8.x4.trans.shared.b16 {%0,%1,%2,%3}, [%4];"
                 : "=r"(r[0]), "=r"(r[1]), "=r"(r[2]), "=r"(r[3]) : "r"(a));
}

// f16 x f16 -> f32 MMA
__device__ __forceinline__ void mma16816(float* c, const uint32_t* a,
                                         uint32_t b0, uint32_t b1) {
    asm volatile(
        "mma.sync.aligned.m16n8k16.row.col.f32.f16.f16.f32 "
        "{%0,%1,%2,%3},{%4,%5,%6,%7},{%8,%9},{%0,%1,%2,%3};"
        : "+f"(c[0]), "+f"(c[1]), "+f"(c[2]), "+f"(c[3])
        : "r"(a[0]), "r"(a[1]), "r"(a[2]), "r"(a[3]), "r"(b0), "r"(b1));
}

__device__ __forceinline__ uint32_t pack_half2(float a, float b) {
    __half2 t;
    t.x = __float2half(a);
    t.y = __float2half(b);
    return *reinterpret_cast<uint32_t*>(&t);
}

// ============================================================================
// Scratch (static device allocations)
// ============================================================================
#define PART_STRIDE ((long)16 * TXT * HIDDEN)   // floats per split-K partial
#define NSPLIT 4

__device__ __half g_ahi[NB * SQ * HIDDEN];            // hidden-hi, then hs-hi
__device__ __half g_qhi[NB * SQ * HIDDEN];
__device__ __half g_ehi[NB * ENC * CROSS];
__device__ __half g_wq[HIDDEN * HIDDEN];              // [K][N] row-major fp16
__device__ __half g_w4[4 * HIDDEN * CROSS];           // wk, wv, wkip, wvip [K][N]
__device__ __half g_wo[HIDDEN * HIDDEN];
__device__ __half g_kv[4 * NB * TXT * HIDDEN];        // k,v,ipk,ipv
__device__ float g_part[NSPLIT * 16 * TXT * HIDDEN];  // split-K partials

// ============================================================================
// Merged prep: pure fp32 -> fp16 converts of 6 weights + 2 activations.
// ============================================================================
struct PrepArgs {
    const float* src[8];
    __half* dst[8];
    int blkOff[9];
};

__global__ __launch_bounds__(256)
void prep_all(PrepArgs p)
{
    const int bid = blockIdx.x;
    int s = 0;
    #pragma unroll
    for (int k = 1; k < 8; k++)
        if (bid >= p.blkOff[k]) s = k;
    const long i = (long)(bid - p.blkOff[s]) * 256 + threadIdx.x;
    float4 x = ((const float4*)p.src[s])[i];
    ((uint2*)p.dst[s])[i] = make_uint2(pack_half2(x.x, x.y), pack_half2(x.z, x.w));
}

// ============================================================================
// Shared GEMM pieces: CTA 128x128x64 (BK=64), 8 warps, warp 32x64, cp.async
// double buffer, pure fp16. A row-major (ldsm), B row-major [K][N] (ldsm.trans).
// ============================================================================
#define LDSA_ROW 144
#define LDSB_ROW 272
#define OFF_A   0
#define OFF_B   18432                 // 128 * 144
#define STGBUF  (18432 + 64 * 272)    // 35840
#define SMEM_TOT (2 * STGBUF)         // 71680

// Interleaved per-accumulator compute (do NOT burst-reorder; see R8).
__device__ __forceinline__ void gemm_stage_compute(
    uint32_t base, uint32_t aoffs, uint32_t boffs, float acc[2][8][4])
{
    const uint32_t aA = base + OFF_A;
    const uint32_t bB = base + OFF_B;
    #pragma unroll
    for (int ks = 0; ks < 4; ks++) {
        uint32_t Ah[2][4];
        #pragma unroll
        for (int mi = 0; mi < 2; mi++)
            ldsm_x4(Ah[mi], aA + aoffs + mi * 16 * LDSA_ROW + ks * 32);
        #pragma unroll
        for (int nq = 0; nq < 4; nq++) {
            uint32_t Bh[4];
            ldsm_x4_t(Bh, bB + boffs + ks * 16 * LDSB_ROW + nq * 32);
            #pragma unroll
            for (int mi = 0; mi < 2; mi++) {
                mma16816(acc[mi][nq * 2 + 0], Ah[mi], Bh[0], Bh[1]);
                mma16816(acc[mi][nq * 2 + 1], Ah[mi], Bh[2], Bh[3]);
            }
        }
    }
}

// kv packed-row map: parts 0-2 text K (4x77 rows), 3-5 text V, 6 ipK (16), 7 ipV.
__device__ __forceinline__ bool kv_map(int part, int r, long& aRow, long& cRow)
{
    aRow = 0; cRow = 0;
    if (part < 6) {
        int R = (part % 3) * 128 + r;
        if (R >= 4 * TXT) return false;
        int batch = R / TXT, rr = R - batch * TXT;
        aRow = (long)batch * ENC + rr;
        cRow = (long)(((part < 3 ? 0 : 1) * 4 + batch) * TXT + rr);
        return true;
    } else {
        if (r >= 16) return false;
        int batch = r >> 2, rr = r & 3;
        aRow = (long)batch * ENC + TXT + rr;
        cRow = (long)(((part == 6 ? 2 : 3) * 4 + batch) * TXT + rr);
        return true;
    }
}

// ============================================================================
// Merged Q-projection + packed split-K kv-projection GEMM (BK=64).
// ============================================================================
struct QKVArgs {
    const __half *ahi, *ehi;
    const __half *wq, *w4;
    __half *qhi;
    float* pbuf;
};

__global__ __launch_bounds__(256, 2)
void hmma_gemm_qkv(QKVArgs args)
{
    extern __shared__ __align__(16) char smx[];
    const uint32_t smb = smem_to_u32(smx);
    const int tid = threadIdx.x;
    const int bid = blockIdx.x;
    const bool isQ = bid < 1280;

    const int lr  = tid >> 3;
    const int cch = tid & 7;
    const int br  = tid >> 4;
    const int bcc = tid & 15;

    const __half *Ahi, *Bm;
    int K, NS, kBase, colBase, rowBase = 0, part = 0, split = 0;
    int aRow[4];
    int aBytes[4];

    if (isQ) {
        rowBase = (bid / 10) * 128;
        colBase = (bid % 10) * 128;
        Ahi = args.ahi;
        Bm = args.wq;
        K = HIDDEN; NS = 20; kBase = 0;
        #pragma unroll
        for (int i = 0; i < 4; i++) {
            aRow[i] = rowBase + lr + i * 32;
            aBytes[i] = 16;
        }
    } else {
        const int t = bid - 1280;
        colBase = (t % 10) * 128;
        part = (t / 10) & 7;
        split = t / 80;
        const int gemm = part < 3 ? 0 : (part < 6 ? 1 : (part == 6 ? 2 : 3));
        Ahi = args.ehi;
        Bm = args.w4 + (long)gemm * HIDDEN * CROSS;
        K = CROSS; NS = 8; kBase = split * 512;
        #pragma unroll
        for (int i = 0; i < 4; i++) {
            long ar, cr;
            aBytes[i] = kv_map(part, lr + i * 32, ar, cr) ? 16 : 0;
            aRow[i] = (int)ar;
        }
    }

    const int warp = tid >> 5, lane = tid & 31;
    const int wm = warp >> 1, wn = warp & 1;
    const int m0 = wm * 32, n0 = wn * 64;

    const uint32_t aoffs = (uint32_t)((m0 + (lane & 15)) * LDSA_ROW + (lane >> 4) * 16);
    const uint32_t boffs = (uint32_t)(((((lane >> 3) & 1) * 8 + (lane & 7)) * LDSB_ROW)
                                      + ((lane >> 4) & 1) * 16 + n0 * 2);

    float acc[2][8][4];
    #pragma unroll
    for (int mi = 0; mi < 2; mi++)
        #pragma unroll
        for (int nj = 0; nj < 8; nj++)
            #pragma unroll
            for (int t = 0; t < 4; t++) acc[mi][nj][t] = 0.f;

    auto load_stage = [&](int s) {
        const int b = s & 1;
        const int k0 = kBase + (s << 6);
        #pragma unroll
        for (int i = 0; i < 4; i++) {
            const int r = lr + i * 32;
            uint32_t d = smb + (uint32_t)(b * STGBUF + OFF_A + r * LDSA_ROW + cch * 16);
            long go = (long)aRow[i] * K + k0 + cch * 8;
            cp_async16(d, Ahi + go, aBytes[i]);
        }
        #pragma unroll
        for (int i = 0; i < 4; i++) {
            const int r = br + i * 16;
            uint32_t d = smb + (uint32_t)(b * STGBUF + OFF_B + r * LDSB_ROW + bcc * 16);
            long gb = (long)(k0 + r) * HIDDEN + colBase + bcc * 8;
            cp_async16(d, Bm + gb, 16);
        }
        CP_COMMIT();
    };

    load_stage(0);
    for (int s = 0; s < NS; ++s) {
        if (s + 1 < NS) {
            load_stage(s + 1);
            CP_WAIT(1);
        } else {
            CP_WAIT(0);
        }
        __syncthreads();
        gemm_stage_compute(smb + (s & 1) * STGBUF, aoffs, boffs, acc);
        __syncthreads();
    }

    // Epilogue
    const int g = lane >> 2, tig = lane & 3;
    if (isQ) {
        #pragma unroll
        for (int mi = 0; mi < 2; mi++) {
            #pragma unroll
            for (int nj = 0; nj < 8; nj++) {
                const int r0 = rowBase + m0 + mi * 16 + g;
                const int col = colBase + n0 + nj * 8 + tig * 2;
                #pragma unroll
                for (int rr = 0; rr < 2; rr++) {
                    long o = (long)(r0 + rr * 8) * HIDDEN + col;
                    *(uint32_t*)(args.qhi + o) =
                        pack_half2(acc[mi][nj][rr * 2 + 0], acc[mi][nj][rr * 2 + 1]);
                }
            }
        }
    } else {
        float* pout = args.pbuf + (long)split * PART_STRIDE;
        #pragma unroll
        for (int mi = 0; mi < 2; mi++) {
            #pragma unroll
            for (int nj = 0; nj < 8; nj++) {
                const int r0 = m0 + mi * 16 + g;
                const int col = colBase + n0 + nj * 8 + tig * 2;
                long aR, cR;
                if (kv_map(part, r0, aR, cR))
                    *(float2*)(pout + cR * HIDDEN + col) =
                        make_float2(acc[mi][nj][0], acc[mi][nj][1]);
                if (kv_map(part, r0 + 8, aR, cR))
                    *(float2*)(pout + cR * HIDDEN + col) =
                        make_float2(acc[mi][nj][2], acc[mi][nj][3]);
            }
        }
    }
}

// ============================================================================
// Out-projection GEMM (BK=64, trans-B, pure fp16, fused bias+resid).
// ============================================================================
struct GemmArgs {
    const __half *Ahi, *Bm;
    float* C;
    int K, ldc;
    const float *bias, *resid;
};

__global__ __launch_bounds__(256, 2)
void hmma_gemm(GemmArgs args)
{
    extern __shared__ __align__(16) char smx[];
    const uint32_t smb = smem_to_u32(smx);
    const int tid = threadIdx.x;

    const __half* Ahi = args.Ahi;
    const __half* Bm = args.Bm;
    const int K = args.K, ldc = args.ldc;

    const int rowBase = blockIdx.y * 128;
    const int colBase = blockIdx.x * 128;
    const int NS = K >> 6;
    const int lr  = tid >> 3;
    const int cch = tid & 7;
    const int br  = tid >> 4;
    const int bcc = tid & 15;

    const int warp = tid >> 5, lane = tid & 31;
    const int wm = warp >> 1, wn = warp & 1;
    const int m0 = wm * 32, n0 = wn * 64;

    const uint32_t aoffs = (uint32_t)((m0 + (lane & 15)) * LDSA_ROW + (lane >> 4) * 16);
    const uint32_t boffs = (uint32_t)(((((lane >> 3) & 1) * 8 + (lane & 7)) * LDSB_ROW)
                                      + ((lane >> 4) & 1) * 16 + n0 * 2);

    float acc[2][8][4];
    #pragma unroll
    for (int mi = 0; mi < 2; mi++)
        #pragma unroll
        for (int nj = 0; nj < 8; nj++)
            #pragma unroll
            for (int t = 0; t < 4; t++) acc[mi][nj][t] = 0.f;

    auto load_stage = [&](int s) {
        const int b = s & 1;
        const int k0 = s << 6;
        #pragma unroll
        for (int i = 0; i < 4; i++) {
            const int r = lr + i * 32;
            uint32_t d = smb + (uint32_t)(b * STGBUF + OFF_A + r * LDSA_ROW + cch * 16);
            long go = (long)(rowBase + r) * K + k0 + cch * 8;
            cp_async16(d, Ahi + go, 16);
        }
        #pragma unroll
        for (int i = 0; i < 4; i++) {
            const int r = br + i * 16;
            uint32_t d = smb + (uint32_t)(b * STGBUF + OFF_B + r * LDSB_ROW + bcc * 16);
            long gb = (long)(k0 + r) * HIDDEN + colBase + bcc * 8;
            cp_async16(d, Bm + gb, 16);
        }
        CP_COMMIT();
    };

    load_stage(0);
    for (int s = 0; s < NS; ++s) {
        if (s + 1 < NS) {
            load_stage(s + 1);
            CP_WAIT(1);
        } else {
            CP_WAIT(0);
        }
        __syncthreads();
        gemm_stage_compute(smb + (s & 1) * STGBUF, aoffs, boffs, acc);
        __syncthreads();
    }

    // Epilogue: fp32 + bias + residual
    const int g = lane >> 2, tig = lane & 3;
    const float* bias = args.bias;
    const float* resid = args.resid;
    #pragma unroll
    for (int mi = 0; mi < 2; mi++) {
        #pragma unroll
        for (int nj = 0; nj < 8; nj++) {
            const int r0 = rowBase + m0 + mi * 16 + g;
            const int col = colBase + n0 + nj * 8 + tig * 2;
            float2 v0 = make_float2(acc[mi][nj][0], acc[mi][nj][1]);
            float2 v1 = make_float2(acc[mi][nj][2], acc[mi][nj][3]);
            const float2 bi = *(const float2*)(bias + col);
            v0.x += bi.x; v0.y += bi.y;
            v1.x += bi.x; v1.y += bi.y;
            const float2 rr0 = *(const float2*)(resid + (long)r0 * ldc + col);
            v0.x += rr0.x; v0.y += rr0.y;
            const float2 rr1 = *(const float2*)(resid + (long)(r0 + 8) * ldc + col);
            v1.x += rr1.x; v1.y += rr1.y;
            *(float2*)(args.C + (long)r0 * ldc + col)       = v0;
            *(float2*)(args.C + (long)(r0 + 8) * ldc + col) = v1;
        }
    }
}

// Sum NSPLIT split-K partials -> kv fp16.
__global__ __launch_bounds__(256)
void reduce_split_kv(const float* __restrict__ part, __half* __restrict__ hi)
{
    const long n4 = PART_STRIDE / 4;
    long i = (long)blockIdx.x * 256 + threadIdx.x;
    if (i >= n4) return;
    const float4* p4 = (const float4*)part;
    float4 s = p4[i];
    #pragma unroll
    for (int k = 1; k < NSPLIT; k++) {
        float4 t = p4[i + (long)k * n4];
        s.x += t.x; s.y += t.y; s.z += t.z; s.w += t.w;
    }
    ((uint2*)hi)[i] = make_uint2(pack_half2(s.x, s.y), pack_half2(s.z, s.w));
}

// ============================================================================
// HMMA flash attention: CTA = 256 q-rows x 96 keys (77 text + pad + 4 ip @80).
// 8 warps, each warp does 16 rows of tile0 then 16 rows of tile1 (K/V reused).
// Pure fp16. V [key][dim] + ldsm.trans. Writes hs as fp16.
// ============================================================================
#define AROW 144
#define KROW 144
#define OFF_Q  0
#define OFF_K  (256 * AROW)                 // 36864
#define OFF_V  (OFF_K + 96 * KROW)          // 50688
#define SMEM_ATTN (OFF_V + 96 * KROW)       // 64512

__global__ __launch_bounds__(256)
void attn_mma(const __half* __restrict__ qhi,
              const __half* __restrict__ kv,
              __half* __restrict__ ohi)
{
    extern __shared__ __align__(16) char smx[];
    const uint32_t smb = smem_to_u32(smx);
    const int tid = threadIdx.x;
    const int b = blockIdx.z, h = blockIdx.y;
    const int rowBase = blockIdx.x * 256;
    const long SLAB = (long)NB * TXT * HIDDEN;

    // Q tile: 256 rows x 64 dims
    #pragma unroll
    for (int i = 0; i < 8; i++) {
        int idx = tid + i * 256;
        int r = idx >> 3, c = idx & 7;
        long src = ((long)b * SQ + rowBase + r) * HIDDEN + h * 64 + c * 8;
        cp_async16(smb + OFF_Q + (uint32_t)(r * AROW + c * 16), qhi + src, 16);
    }
    // K tile: rows 0-76 text K, 80-83 ipK, rest zero
    #pragma unroll
    for (int i = 0; i < 3; i++) {
        int idx = tid + i * 256;
        int r = idx >> 3, c = idx & 7;
        int bytes = 0;
        long src = 0;
        if (r < TXT) {
            bytes = 16;
            src = (long)b * TXT * HIDDEN + (long)r * HIDDEN + h * 64 + c * 8;
        } else if (r >= 80 && r < 80 + NTOK) {
            bytes = 16;
            src = 2 * SLAB + (long)b * TXT * HIDDEN + (long)(r - 80) * HIDDEN + h * 64 + c * 8;
        }
        cp_async16(smb + OFF_K + (uint32_t)(r * KROW + c * 16), kv + src, bytes);
    }
    // V tile: rows 0-76 text V, 80-83 ipV, [key][dim]
    #pragma unroll
    for (int i = 0; i < 3; i++) {
        int idx = tid + i * 256;
        int r = idx >> 3, c = idx & 7;
        int bytes = 0;
        long src = 0;
        if (r < TXT) {
            bytes = 16;
            src = SLAB + (long)b * TXT * HIDDEN + (long)r * HIDDEN + h * 64 + c * 8;
        } else if (r >= 80 && r < 80 + NTOK) {
            bytes = 16;
            src = 3 * SLAB + (long)b * TXT * HIDDEN + (long)(r - 80) * HIDDEN + h * 64 + c * 8;
        }
        cp_async16(smb + OFF_V + (uint32_t)(r * KROW + c * 16), kv + src, bytes);
    }
    CP_COMMIT();
    CP_WAIT(0);
    __syncthreads();

    const int warp = tid >> 5, lane = tid & 31;
    const int tig = lane & 3;
    const bool ipOn = (b & 1);
    const uint32_t kbase = smb + OFF_K
        + (uint32_t)((((lane >> 4) & 1) * 8 + (lane & 7)) * KROW + ((lane >> 3) & 1) * 16);
    const uint32_t vtbase = smb + OFF_V
        + (uint32_t)((((lane >> 3) & 1) * 8 + (lane & 7)) * KROW + ((lane >> 4) & 1) * 16);

    #pragma unroll
    for (int tile = 0; tile < 2; tile++) {
        const int m0 = tile * 128 + warp * 16;
        const uint32_t aoffs = smb + OFF_Q
            + (uint32_t)((m0 + (lane & 15)) * AROW + (lane >> 4) * 16);

        // S = Q K^T (tiles j=0..10; j=11 is pure padding -> stays 0)
        float s[12][4];
        #pragma unroll
        for (int j = 0; j < 12; j++)
            #pragma unroll
            for (int e = 0; e < 4; e++) s[j][e] = 0.f;

        #pragma unroll
        for (int ks = 0; ks < 4; ks++) {
            uint32_t Qh[4];
            ldsm_x4(Qh, aoffs + ks * 32);
            #pragma unroll
            for (int t = 0; t < 6; t++) {
                uint32_t Bh[4];
                ldsm_x4(Bh, kbase + t * 16 * KROW + ks * 32);
                mma16816(s[2 * t + 0], Qh, Bh[0], Bh[1]);
                if (t < 5) mma16816(s[2 * t + 1], Qh, Bh[2], Bh[3]);
            }
        }

        // scale + mask + dual softmax
        float mx[2]  = {-1e30f, -1e30f};
        float mx2[2] = {-1e30f, -1e30f};
        #pragma unroll
        for (int j = 0; j < 10; j++)
            #pragma unroll
            for (int e = 0; e < 4; e++) {
                int col = j * 8 + tig * 2 + (e & 1);
                float v = s[j][e] * 0.125f;
                s[j][e] = (col < TXT) ? v : -1e30f;
                mx[e >> 1] = fmaxf(mx[e >> 1], s[j][e]);
            }
        #pragma unroll
        for (int j = 10; j < 12; j++)
            #pragma unroll
            for (int e = 0; e < 4; e++) {
                int col = j * 8 + tig * 2 + (e & 1);
                float v = s[j][e] * 0.125f;
                s[j][e] = (col >= 80 && col < 80 + NTOK) ? v : -1e30f;
                mx2[e >> 1] = fmaxf(mx2[e >> 1], s[j][e]);
            }
        #pragma unroll
        for (int off = 1; off <= 2; off <<= 1) {
            mx[0]  = fmaxf(mx[0],  __shfl_xor_sync(0xffffffffu, mx[0],  off));
            mx[1]  = fmaxf(mx[1],  __shfl_xor_sync(0xffffffffu, mx[1],  off));
            mx2[0] = fmaxf(mx2[0], __shfl_xor_sync(0xffffffffu, mx2[0], off));
            mx2[1] = fmaxf(mx2[1], __shfl_xor_sync(0xffffffffu, mx2[1], off));
        }
        float l[2] = {0.f, 0.f}, l2[2] = {0.f, 0.f};
        #pragma unroll
        for (int j = 0; j < 10; j++)
            #pragma unroll
            for (int e = 0; e < 4; e++) {
                float p = __expf(s[j][e] - mx[e >> 1]);
                s[j][e] = p;
                l[e >> 1] += p;
            }
        #pragma unroll
        for (int j = 10; j < 12; j++)
            #pragma unroll
            for (int e = 0; e < 4; e++) {
                float p = __expf(s[j][e] - mx2[e >> 1]);
                s[j][e] = p;
                l2[e >> 1] += p;
            }
        #pragma unroll
        for (int off = 1; off <= 2; off <<= 1) {
            l[0]  += __shfl_xor_sync(0xffffffffu, l[0],  off);
            l[1]  += __shfl_xor_sync(0xffffffffu, l[1],  off);
            l2[0] += __shfl_xor_sync(0xffffffffu, l2[0], off);
            l2[1] += __shfl_xor_sync(0xffffffffu, l2[1], off);
        }
        float inv[2], inv2[2];
        inv[0] = 1.f / l[0];
        inv[1] = 1.f / l[1];
        inv2[0] = ipOn ? 1.f / l2[0] : 0.f;
        inv2[1] = ipOn ? 1.f / l2[1] : 0.f;
        #pragma unroll
        for (int j = 0; j < 10; j++)
            #pragma unroll
            for (int e = 0; e < 4; e++) s[j][e] *= inv[e >> 1];
        #pragma unroll
        for (int j = 10; j < 12; j++)
            #pragma unroll
            for (int e = 0; e < 4; e++) s[j][e] *= inv2[e >> 1];

        // PV via ldsm.trans on V[key][dim]
        float out[8][4];
        #pragma unroll
        for (int d = 0; d < 8; d++)
            #pragma unroll
            for (int e = 0; e < 4; e++) out[d][e] = 0.f;

        #pragma unroll
        for (int kk = 0; kk < 6; kk++) {
            uint32_t ah[4];
            #pragma unroll
            for (int r = 0; r < 4; r++) {
                const int t = 2 * kk + (r >> 1);
                const int pi = (r & 1) * 2;
                ah[r] = pack_half2(s[t][pi], s[t][pi + 1]);
            }
            #pragma unroll
            for (int d = 0; d < 4; d++) {
                uint32_t Vh[4];
                ldsm_x4_t(Vh, vtbase + kk * 16 * KROW + d * 32);
                mma16816(out[2 * d + 0], ah, Vh[0], Vh[1]);
                mma16816(out[2 * d + 1], ah, Vh[2], Vh[3]);
            }
        }

        // write hs fp16
        const int g = lane >> 2;
        const long row0 = (long)b * SQ + rowBase + m0 + g;
        #pragma unroll
        for (int d = 0; d < 8; d++) {
            const int col = h * 64 + d * 8 + tig * 2;
            #pragma unroll
            for (int rr = 0; rr < 2; rr++) {
                long o = (row0 + rr * 8) * HIDDEN + col;
                *(uint32_t*)(ohi + o) = pack_half2(out[d][rr * 2 + 0], out[d][rr * 2 + 1]);
            }
        }
    }
}

// ============================================================================
// Launcher
// ============================================================================
extern "C" void kernel_launch(void* const* d_in, const int* in_sizes, int n_in,
                              void* d_out, int out_size)
{
    const float* hidden = (const float*)d_in[0];
    const float* enc    = (const float*)d_in[1];
    const float* Wq     = (const float*)d_in[2];
    const float* Wk     = (const float*)d_in[3];
    const float* Wv     = (const float*)d_in[4];
    const float* Wk_ip  = (const float*)d_in[5];
    const float* Wv_ip  = (const float*)d_in[6];
    const float* Wout   = (const float*)d_in[7];
    const float* b_out  = (const float*)d_in[8];
    float* out = (float*)d_out;

    static bool attr_set = false;
    if (!attr_set) {
        cudaFuncSetAttribute(hmma_gemm, cudaFuncAttributeMaxDynamicSharedMemorySize, SMEM_TOT);
        cudaFuncSetAttribute(hmma_gemm_qkv, cudaFuncAttributeMaxDynamicSharedMemorySize, SMEM_TOT);
        cudaFuncSetAttribute(attn_mma, cudaFuncAttributeMaxDynamicSharedMemorySize, SMEM_ATTN);
        attr_set = true;
    }

    __half *ahi, *qhi, *ehi, *wq, *w4, *wo, *kv;
    float* pbuf;
    cudaGetSymbolAddress((void**)&ahi, g_ahi);
    cudaGetSymbolAddress((void**)&qhi, g_qhi);
    cudaGetSymbolAddress((void**)&ehi, g_ehi);
    cudaGetSymbolAddress((void**)&wq,  g_wq);
    cudaGetSymbolAddress((void**)&w4,  g_w4);
    cudaGetSymbolAddress((void**)&wo,  g_wo);
    cudaGetSymbolAddress((void**)&kv,  g_kv);
    cudaGetSymbolAddress((void**)&pbuf, g_part);

    const int M_big = NB * SQ;  // 16384
    const long WSLAB = (long)HIDDEN * CROSS;

    // 1) merged prep: pure converts (weights kept [K][N]; B uses ldsm.trans)
    {
        PrepArgs p;
        p.src[0] = Wq;    p.dst[0] = wq;
        p.src[1] = Wk;    p.dst[1] = w4 + 0 * WSLAB;
        p.src[2] = Wv;    p.dst[2] = w4 + 1 * WSLAB;
        p.src[3] = Wk_ip; p.dst[3] = w4 + 2 * WSLAB;
        p.src[4] = Wv_ip; p.dst[4] = w4 + 3 * WSLAB;
        p.src[5] = Wout;  p.dst[5] = wo;
        p.src[6] = enc;   p.dst[6] = ehi;
        p.src[7] = hidden; p.dst[7] = ahi;
        p.blkOff[0] = 0;
        p.blkOff[1] = 1600;
        p.blkOff[2] = 1600 + 2560;
        p.blkOff[3] = 1600 + 2 * 2560;
        p.blkOff[4] = 1600 + 3 * 2560;
        p.blkOff[5] = 1600 + 4 * 2560;
        p.blkOff[6] = 3200 + 4 * 2560;
        p.blkOff[7] = 3200 + 4 * 2560 + 648;
        const int total = 3200 + 4 * 2560 + 648 + 20480;   // 34568
        prep_all<<<total, 256>>>(p);
    }

    // 2) merged Q projection + packed split-K kv projections (1600 CTAs)
    {
        QKVArgs a;
        a.ahi = ahi; a.ehi = ehi;
        a.wq = wq; a.w4 = w4;
        a.qhi = qhi; a.pbuf = pbuf;
        hmma_gemm_qkv<<<1280 + NSPLIT * 80, 256, SMEM_TOT>>>(a);
    }

    // 3) reduce split-K partials -> kv fp16
    {
        long n4 = PART_STRIDE / 4;
        reduce_split_kv<<<(int)((n4 + 255) / 256), 256>>>(pbuf, kv);
    }

    // 4) HMMA attention, 256 q-rows per CTA -> hs fp16 (reuses g_ahi)
    attn_mma<<<dim3(SQ / 256, NHEADS, NB), 256, SMEM_ATTN>>>(qhi, kv, ahi);

    // 5) out = hs @ Wout + b_out + residual (fp32)
    {
        GemmArgs a = {ahi, wo, out, HIDDEN, HIDDEN, b_out, hidden};
        hmma_gemm<<<dim3(HIDDEN / 128, M_big / 128, 1), 256, SMEM_TOT>>>(a);
    }
}